// round 12
// baseline (speedup 1.0000x reference)
#include <cuda_runtime.h>
#include <cuda_bf16.h>
#include <cuda_fp16.h>
#include <cstdint>
#include <cstring>

#define B_SZ 2
#define SEQL 2048
#define DMODEL 2048
#define DINNER 4096
#define DSTATE 128
#define HEADDIM 64
#define NHEADS 64
#define CHUNKL 256
#define NCHUNK 8
#define CONV_DIM 4352     // DINNER + 2*DSTATE
#define D_IN_PROJ 8512    // 2*DINNER + 2*DSTATE + NHEADS
#define DIP_PAD 8576      // 67*128
#define EPSV 1e-5f

// ---------------- scratch ----------------
__device__ float g_zx[B_SZ*SEQL*D_IN_PROJ];
__device__ float g_dt[B_SZ*SEQL*NHEADS];
__device__ float g_Acs[B_SZ*NHEADS*NCHUNK*CHUNKL];
__device__ float g_ss[B_SZ*SEQL];                                      // row sum-of-squares
// fp16 gemm operands
__device__ __half g_xh[B_SZ*SEQL*DMODEL];
__device__ __half g_wih[(size_t)DIP_PAD*DMODEL];
__device__ __half g_ynh[B_SZ*SEQL*DINNER];
__device__ __half g_owh[(size_t)DMODEL*DINNER];
// fp16 activations / SSM operands
__device__ __half g_xs[B_SZ*SEQL*DINNER];
__device__ __half g_B[B_SZ*SEQL*DSTATE];
__device__ __half g_C[B_SZ*SEQL*DSTATE];
__device__ __half g_BT[B_SZ*DSTATE*SEQL];
__device__ __half g_XdT[(size_t)B_SZ*NHEADS*HEADDIM*SEQL];
__device__ __half g_XdecT[(size_t)B_SZ*NHEADS*HEADDIM*SEQL];
__device__ __half g_statesh[(size_t)B_SZ*NCHUNK*NHEADS*HEADDIM*DSTATE];
__device__ __half g_prev[(size_t)B_SZ*NCHUNK*NHEADS*HEADDIM*DSTATE];
__device__ __half g_ygh[B_SZ*SEQL*DINNER];                             // gated pre-norm fp16

__device__ __forceinline__ float siluf(float a) { return a / (1.f + expf(-a)); }

// ================= common HMMA helpers =================
__device__ __forceinline__ void mma_fp16(float* c, const uint32_t* a, const uint32_t* b) {
    asm volatile(
        "mma.sync.aligned.m16n8k16.row.col.f32.f16.f16.f32 "
        "{%0,%1,%2,%3}, {%4,%5,%6,%7}, {%8,%9}, {%0,%1,%2,%3};"
        : "+f"(c[0]), "+f"(c[1]), "+f"(c[2]), "+f"(c[3])
        : "r"(a[0]), "r"(a[1]), "r"(a[2]), "r"(a[3]), "r"(b[0]), "r"(b[1]));
}
__device__ __forceinline__ void ldsm4(uint32_t* r, uint32_t addr) {
    asm volatile("ldmatrix.sync.aligned.m8n8.x4.shared.b16 {%0,%1,%2,%3}, [%4];"
        : "=r"(r[0]), "=r"(r[1]), "=r"(r[2]), "=r"(r[3]) : "r"(addr));
}
__device__ __forceinline__ void cp16(uint32_t dst, const void* src) {
    asm volatile("cp.async.cg.shared.global [%0], [%1], 16;" :: "r"(dst), "l"(src));
}
__device__ __forceinline__ uint32_t smem_u32(const void* p) {
    uint32_t a;
    asm("{ .reg .u64 t; cvta.to.shared.u64 t, %1; cvt.u32.u64 %0, t; }" : "=r"(a) : "l"(p));
    return a;
}
__device__ __forceinline__ uint32_t packh2(__half a, __half b) {
    __half2 h = __halves2half2(a, b);
    uint32_t u; memcpy(&u, &h, 4); return u;
}

// ================= persistent fp16 HMMA GEMM, BK=64, 3 stages =================
#define OPW64 4096
#define STG64 (2 * OPW64)
#define GEMM1_SMEM (3 * STG64 * 4)        // 98304 B

__device__ __forceinline__ void load_op64(uint32_t sbase_b, const __half* g, int ldk, int tid) {
#pragma unroll
    for (int it = 0; it < 4; it++) {
        int v = tid + (it << 8);
        int r = v >> 3, ch = v & 7;
        int sch = ch ^ (r & 7);
        cp16(sbase_b + (r * 32 + (sch << 2)) * 4, g + (size_t)r * ldk + (ch << 3));
    }
}

__global__ __launch_bounds__(256, 2) void gemm_hmma_fp16(
    const __half* __restrict__ A, const __half* __restrict__ B,
    float* __restrict__ C, int M, int Nreal, int K, int nTileN)
{
    extern __shared__ uint32_t sw[];
    const uint32_t sb = smem_u32(sw);
    const int tid = threadIdx.x, wid = tid >> 5, lane = tid & 31;
    const int warp_m = wid & 1, warp_n = wid >> 1;
    const int KT = K >> 6;
    const int nTiles = nTileN * (M >> 7);

    const int rowA = warp_m * 64 + ((lane >> 3) & 1) * 8 + (lane & 7);
    const int cA0  = lane >> 4;
    const int rowB = warp_n * 32 + ((lane >> 4) & 1) * 8 + (lane & 7);
    const int cB0  = (lane >> 3) & 1;

    for (int tile = blockIdx.x; tile < nTiles; tile += gridDim.x) {
        const int n0 = (tile % nTileN) << 7;
        const int m0 = (tile / nTileN) << 7;
        const __half* Ab = A + (size_t)m0 * K;
        const __half* Bb = B + (size_t)n0 * K;

        __syncthreads();   // protect smem reuse across tiles

        float acc[4][4][4];
#pragma unroll
        for (int i = 0; i < 4; i++)
#pragma unroll
            for (int j = 0; j < 4; j++)
#pragma unroll
                for (int q = 0; q < 4; q++) acc[i][j][q] = 0.f;

#pragma unroll
        for (int s = 0; s < 2; s++) {
            int koff = s << 6;
            load_op64(sb + (s * STG64) * 4, Ab + koff, K, tid);
            load_op64(sb + (s * STG64 + OPW64) * 4, Bb + koff, K, tid);
            asm volatile("cp.async.commit_group;" ::: "memory");
        }

        int buf = 0;
        for (int kt = 0; kt < KT; kt++) {
            if (kt + 1 < KT) asm volatile("cp.async.wait_group 1;" ::: "memory");
            else             asm volatile("cp.async.wait_group 0;" ::: "memory");
            __syncthreads();
            if (kt + 2 < KT) {
                int s = buf + 2; if (s >= 3) s -= 3;
                int koff = (kt + 2) << 6;
                load_op64(sb + (s * STG64) * 4, Ab + koff, K, tid);
                load_op64(sb + (s * STG64 + OPW64) * 4, Bb + koff, K, tid);
                asm volatile("cp.async.commit_group;" ::: "memory");
            }

            const uint32_t sA = sb + (uint32_t)buf * STG64 * 4u;
            const uint32_t sB = sA + OPW64 * 4u;

#pragma unroll
            for (int kk = 0; kk < 4; kk++) {
                uint32_t a[4][4];
#pragma unroll
                for (int mi = 0; mi < 4; mi++) {
                    int r = rowA + mi * 16;
                    uint32_t off = (r * 32 + ((((kk << 1) + cA0) ^ (r & 7)) << 2)) * 4u;
                    ldsm4(a[mi], sA + off);
                }
#pragma unroll
                for (int np = 0; np < 2; np++) {
                    int r = rowB + np * 16;
                    uint32_t boff = (r * 32 + ((((kk << 1) + cB0) ^ (r & 7)) << 2)) * 4u;
                    uint32_t b[4];
                    ldsm4(b, sB + boff);
#pragma unroll
                    for (int mi = 0; mi < 4; mi++) {
                        mma_fp16(acc[mi][2 * np], a[mi], b);
                        mma_fp16(acc[mi][2 * np + 1], a[mi], b + 2);
                    }
                }
            }
            buf++; if (buf == 3) buf = 0;
        }

#pragma unroll
        for (int mi = 0; mi < 4; mi++) {
            int rg0 = m0 + warp_m * 64 + mi * 16 + (lane >> 2);
#pragma unroll
            for (int ni = 0; ni < 4; ni++) {
                int cg = n0 + warp_n * 32 + ni * 8 + ((lane & 3) << 1);
                if (cg < Nreal) {
                    *(float2*)(C + (size_t)rg0 * Nreal + cg) =
                        make_float2(acc[mi][ni][0], acc[mi][ni][1]);
                    *(float2*)(C + (size_t)(rg0 + 8) * Nreal + cg) =
                        make_float2(acc[mi][ni][2], acc[mi][ni][3]);
                }
            }
        }
    }
}

// ---------------- merged fp32 -> fp16 converts (x, in_proj_w padded, out_proj_w) ----------------
#define CVT_N1 ((long)B_SZ*SEQL*DMODEL)          // 8388608
#define CVT_NS2 ((long)D_IN_PROJ*DMODEL)         // 17432576
#define CVT_NT2 ((long)DIP_PAD*DMODEL)           // 17563648
#define CVT_N3 ((long)DMODEL*DINNER)             // 8388608
#define CVT_B1 ((unsigned)(CVT_N1/4/256))        // 8192
#define CVT_B2 ((unsigned)(CVT_NT2/4/256))       // 17152
#define CVT_B3 ((unsigned)(CVT_N3/4/256))        // 8192

__global__ void cvt_all(const float* __restrict__ x, const float* __restrict__ wi,
                        const float* __restrict__ wo,
                        __half* __restrict__ xh, __half* __restrict__ wih,
                        __half* __restrict__ owh)
{
    unsigned bid = blockIdx.x;
    const float* src; __half* dst; long i, n_src;
    if (bid < CVT_B1) {
        i = ((long)bid * 256 + threadIdx.x) * 4; src = x; dst = xh; n_src = CVT_N1;
    } else if (bid < CVT_B1 + CVT_B2) {
        i = ((long)(bid - CVT_B1) * 256 + threadIdx.x) * 4; src = wi; dst = wih; n_src = CVT_NS2;
    } else {
        i = ((long)(bid - CVT_B1 - CVT_B2) * 256 + threadIdx.x) * 4; src = wo; dst = owh; n_src = CVT_N3;
    }
    float4 v = (i < n_src) ? *(const float4*)(src + i) : make_float4(0.f, 0.f, 0.f, 0.f);
    __half2* dp = (__half2*)(dst + i);
    dp[0] = __floats2half2_rn(v.x, v.y);
    dp[1] = __floats2half2_rn(v.z, v.w);
}

// ---------------- merged conv+silu (fp16 out) and dt softplus+cumsum ----------------
// blocks [0,1024): dt_scan; blocks [1024, 1024+272): conv (256 threads each)
__global__ void conv_dt_kernel(const float* __restrict__ conv_w,
                               const float* __restrict__ conv_b,
                               const float* __restrict__ dt_bias,
                               const float* __restrict__ A_log)
{
    __shared__ float s[CHUNKL];
    if (blockIdx.x < 1024) {
        int idx = blockIdx.x;
        int c = idx % NCHUNK; idx /= NCHUNK;
        int h = idx % NHEADS;
        int b = idx / NHEADS;
        int l = threadIdx.x;
        int t = c * CHUNKL + l;
        float raw = g_zx[(size_t)(b * SEQL + t) * D_IN_PROJ + DINNER + CONV_DIM + h];
        float xv = raw + dt_bias[h];
        float dt = (xv > 20.f) ? xv : log1pf(expf(xv));
        g_dt[(b * SEQL + t) * NHEADS + h] = dt;
        float dA = dt * (-expf(A_log[h]));
        s[l] = dA;
        __syncthreads();
        for (int off = 1; off < CHUNKL; off <<= 1) {
            float v = (l >= off) ? s[l - off] : 0.f;
            __syncthreads();
            s[l] += v;
            __syncthreads();
        }
        g_Acs[((b * NHEADS + h) * NCHUNK + c) * CHUNKL + l] = s[l];
    } else {
        int bid2 = blockIdx.x - 1024;
        int chunk = bid2 % 17; bid2 /= 17;
        int b = bid2 & 1;
        int t0 = (bid2 >> 1) * 256;
        int c = chunk * 256 + threadIdx.x;
        float w0 = conv_w[c * 4 + 0], w1 = conv_w[c * 4 + 1];
        float w2 = conv_w[c * 4 + 2], w3 = conv_w[c * 4 + 3];
        float bias = conv_b[c];
        const float* src = g_zx + (size_t)b * SEQL * D_IN_PROJ + DINNER + c;
        __half* dst; int stride;
        if (c < DINNER) {
            dst = g_xs + (size_t)b * SEQL * DINNER + c;           stride = DINNER;
        } else if (c < DINNER + DSTATE) {
            dst = g_B + (size_t)b * SEQL * DSTATE + (c - DINNER); stride = DSTATE;
        } else {
            dst = g_C + (size_t)b * SEQL * DSTATE + (c - DINNER - DSTATE); stride = DSTATE;
        }
        dst += (size_t)t0 * stride;
        float x0 = (t0 >= 3) ? src[(size_t)(t0 - 3) * D_IN_PROJ] : 0.f;
        float x1 = (t0 >= 2) ? src[(size_t)(t0 - 2) * D_IN_PROJ] : 0.f;
        float x2 = (t0 >= 1) ? src[(size_t)(t0 - 1) * D_IN_PROJ] : 0.f;
        for (int t = 0; t < 256; t++) {
            float x3 = src[(size_t)(t0 + t) * D_IN_PROJ];
            float a = bias + w0 * x0 + w1 * x1 + w2 * x2 + w3 * x3;
            dst[(size_t)t * stride] = __float2half_rn(siluf(a));
            x0 = x1; x1 = x2; x2 = x3;
        }
    }
}

// ---------------- merged SSM operand transposes: BT (blocks [0,512)) + XdT/XdecT ----------------
__global__ void cvt_ssm_kernel()
{
    __shared__ float xs[64][65];
    __shared__ float dts[64], dec[64];
    __shared__ __half btile[32][34];
    int tid = threadIdx.x;
    if (blockIdx.x < 512) {
        int i = blockIdx.x;
        int t0 = (i & 63) * 32; i >>= 6;
        int n0 = (i & 3) * 32;
        int b = i >> 2;
#pragma unroll
        for (int it = 0; it < 4; it++) {
            int v = tid + it * 256;
            int t = v >> 5, n = v & 31;
            btile[t][n] = g_B[(size_t)(b * SEQL + t0 + t) * DSTATE + n0 + n];
        }
        __syncthreads();
#pragma unroll
        for (int it = 0; it < 2; it++) {
            int v = tid + it * 256;
            int n = v >> 4, tc = (v & 15) << 1;
            size_t o = (size_t)(b * DSTATE + n0 + n) * SEQL + t0 + tc;
            *(__half2*)(g_BT + o) = __halves2half2(btile[tc][n], btile[tc + 1][n]);
        }
    } else {
        int j = blockIdx.x - 512;
        int tt = j & 31; j >>= 5;
        int h = j & 63;
        int b = j >> 6;
        int t0 = tt * 64;
        int c = t0 >> 8;
        const float* acs = g_Acs + ((b * NHEADS + h) * NCHUNK + c) * CHUNKL;
        if (tid < 64) {
            int tl = (t0 & 255) + tid;
            dts[tid] = g_dt[(size_t)(b * SEQL + t0 + tid) * NHEADS + h];
            dec[tid] = __expf(acs[CHUNKL - 1] - acs[tl]);
        }
#pragma unroll
        for (int it = 0; it < 16; it++) {
            int v = tid + it * 256;
            int t = v >> 6, p = v & 63;
            xs[t][p] = __half2float(g_xs[(size_t)(b * SEQL + t0 + t) * DINNER + h * HEADDIM + p]);
        }
        __syncthreads();
#pragma unroll
        for (int it = 0; it < 8; it++) {
            int v = tid + it * 256;
            int p = v >> 5, tc = (v & 31) << 1;
            size_t o = ((size_t)((b * NHEADS + h) * HEADDIM) + p) * SEQL + t0 + tc;
            float x0 = xs[tc][p] * dts[tc];
            float x1 = xs[tc + 1][p] * dts[tc + 1];
            *(__half2*)(g_XdT + o)   = __floats2half2_rn(x0, x1);
            *(__half2*)(g_XdecT + o) = __floats2half2_rn(x0 * dec[tc], x1 * dec[tc + 1]);
        }
    }
}

// ---------------- states (single fp16 HMMA) -> fp16 output ----------------
#define S_A_O 0
#define S_B_O 2048
#define S_STG 6144
#define S_SMEM_BYTES (2 * S_STG * 4)

__global__ __launch_bounds__(256, 2) void states_hmma()
{
    extern __shared__ uint32_t sw[];
    const uint32_t sb = smem_u32(sw);
    int bid = blockIdx.x;
    int h = bid & 63, cc = (bid >> 6) & 7, b = bid >> 9;
    int tid = threadIdx.x, wid = tid >> 5, lane = tid & 31;
    int warp_m = wid >> 2, warp_n = wid & 3;
    const __half* A = g_XdecT + (size_t)((b * NHEADS + h) * HEADDIM) * SEQL + cc * CHUNKL;
    const __half* B = g_BT + (size_t)(b * DSTATE) * SEQL + cc * CHUNKL;

    float acc[2][4][4];
#pragma unroll
    for (int i = 0; i < 2; i++)
#pragma unroll
        for (int j = 0; j < 4; j++)
#pragma unroll
            for (int q = 0; q < 4; q++) acc[i][j][q] = 0.f;

    auto load_stage = [&](int kc, int buf) {
        uint32_t base = (uint32_t)buf * S_STG;
        int koff = kc * 64;
#pragma unroll
        for (int it = 0; it < 2; it++) {
            int v = tid + (it << 8);
            int r = v >> 3, ch = v & 7;
            int sch = ch ^ (r & 7);
            cp16(sb + (base + S_A_O + r * 32 + sch * 4) * 4, A + (size_t)r * SEQL + koff + ch * 8);
        }
#pragma unroll
        for (int it = 0; it < 4; it++) {
            int v = tid + (it << 8);
            int r = v >> 3, ch = v & 7;
            int sch = ch ^ (r & 7);
            cp16(sb + (base + S_B_O + r * 32 + sch * 4) * 4, B + (size_t)r * SEQL + koff + ch * 8);
        }
        asm volatile("cp.async.commit_group;" ::: "memory");
    };

    load_stage(0, 0);
    load_stage(1, 1);

    const int arow = warp_m * 32 + ((lane >> 3) & 1) * 8 + (lane & 7);
    const int cA0 = lane >> 4;
    const int brl = ((lane >> 4) & 1) * 8 + (lane & 7);
    const int cB0 = (lane >> 3) & 1;

    for (int kc = 0; kc < 4; kc++) {
        if (kc < 3) asm volatile("cp.async.wait_group 1;" ::: "memory");
        else        asm volatile("cp.async.wait_group 0;" ::: "memory");
        __syncthreads();
        uint32_t base = (uint32_t)(kc & 1) * S_STG;
#pragma unroll
        for (int kk = 0; kk < 4; kk++) {
            uint32_t a[2][4];
#pragma unroll
            for (int mi = 0; mi < 2; mi++) {
                int r = arow + mi * 16;
                uint32_t w = base + S_A_O + r * 32 + ((((kk << 1) + cA0) ^ (r & 7)) << 2);
                ldsm4(a[mi], sb + w * 4);
            }
#pragma unroll
            for (int np = 0; np < 2; np++) {
                int rb = warp_n * 32 + np * 16 + brl;
                uint32_t w = base + S_B_O + rb * 32 + ((((kk << 1) + cB0) ^ (rb & 7)) << 2);
                uint32_t bf[4];
                ldsm4(bf, sb + w * 4);
#pragma unroll
                for (int mi = 0; mi < 2; mi++) {
                    mma_fp16(acc[mi][2 * np], a[mi], bf);
                    mma_fp16(acc[mi][2 * np + 1], a[mi], bf + 2);
                }
            }
        }
        __syncthreads();
        if (kc + 2 < 4) load_stage(kc + 2, kc & 1);
    }

    __half* out = g_statesh + (size_t)((b * NCHUNK + cc) * NHEADS + h) * HEADDIM * DSTATE;
#pragma unroll
    for (int mi = 0; mi < 2; mi++) {
        int r0 = warp_m * 32 + mi * 16 + (lane >> 2);
#pragma unroll
        for (int ni = 0; ni < 4; ni++) {
            int col = warp_n * 32 + ni * 8 + 2 * (lane & 3);
            *(__half2*)(out + (size_t)r0 * DSTATE + col) =
                __floats2half2_rn(acc[mi][ni][0], acc[mi][ni][1]);
            *(__half2*)(out + (size_t)(r0 + 8) * DSTATE + col) =
                __floats2half2_rn(acc[mi][ni][2], acc[mi][ni][3]);
        }
    }
}

// ---------------- inter-chunk recurrence ----------------
__global__ __launch_bounds__(1024) void prev_kernel()
{
    int b = blockIdx.x >> 6;
    int h = blockIdx.x & 63;
    int tid = threadIdx.x;
    float P[8];
#pragma unroll
    for (int i = 0; i < 8; i++) P[i] = 0.f;
    for (int c = 0; c < NCHUNK; c++) {
        float decay = __expf(g_Acs[((b * NHEADS + h) * NCHUNK + c) * CHUNKL + CHUNKL - 1]);
        size_t base = (size_t)((b * NCHUNK + c) * NHEADS + h) * HEADDIM * DSTATE;
#pragma unroll
        for (int i = 0; i < 8; i++) {
            int e = i * 1024 + tid;
            float v = P[i];
            g_prev[base + e] = __float2half_rn(v);
            P[i] = v * decay + __half2float(g_statesh[base + e]);
        }
    }
}

// ---------------- Y via single fp16 HMMA -> fp16 out + fused sumsq ----------------
#define Y_ACS_O 0
#define Y_C_O 256
#define Y_PV_O (Y_C_O + 4352)
#define Y_B0_O (Y_PV_O + 4352)
#define Y_B1_O (Y_B0_O + 4352)
#define Y_X0_O (Y_B1_O + 4352)
#define Y_X1_O (Y_X0_O + 2304)
#define Y_S_O  (Y_X1_O + 2304)
#define Y_SMEM_BYTES ((Y_S_O + 2304) * 4)

__global__ __launch_bounds__(256, 2) void y_hmma(const float* __restrict__ Dp)
{
    extern __shared__ uint32_t sw[];
    const uint32_t sb = smem_u32(sw);
    float* acs_s = (float*)(sw + Y_ACS_O);
    int bid = blockIdx.x;
    int lt = bid & 3, h = (bid >> 2) & 63, c = (bid >> 8) & 7, b = bid >> 11;
    int tid = threadIdx.x, wid = tid >> 5, lane = tid & 31;
    int warp_m = wid >> 2, warp_n = wid & 3;
    int l0 = lt * 64;
    const int bt0 = b * SEQL + c * CHUNKL;

    acs_s[tid] = g_Acs[((b * NHEADS + h) * NCHUNK + c) * CHUNKL + tid];

    const __half* gB = g_B + (size_t)bt0 * DSTATE;
    const __half* gX = g_XdT + (size_t)((b * NHEADS + h) * HEADDIM) * SEQL + c * CHUNKL;

    auto load_bx = [&](int st, int pbuf) {
        const __half* Bp = gB + (size_t)(st * 64) * DSTATE;
        const __half* Xp = gX + st * 64;
        uint32_t bo = pbuf ? (uint32_t)Y_B1_O : (uint32_t)Y_B0_O;
        uint32_t xo = pbuf ? (uint32_t)Y_X1_O : (uint32_t)Y_X0_O;
#pragma unroll
        for (int it = 0; it < 4; it++) {
            int v = tid + (it << 8);
            int r = v >> 4, ch = v & 15;
            cp16(sb + (bo + r * 68 + ch * 4) * 4, Bp + (size_t)r * DSTATE + ch * 8);
        }
#pragma unroll
        for (int it = 0; it < 2; it++) {
            int v = tid + (it << 8);
            int r = v >> 3, ch = v & 7;
            cp16(sb + (xo + r * 36 + ch * 4) * 4, Xp + (size_t)r * SEQL + ch * 8);
        }
        asm volatile("cp.async.commit_group;" ::: "memory");
    };

    {
        const __half* sC = g_C + (size_t)(bt0 + l0) * DSTATE;
        size_t pb = (size_t)((b * NCHUNK + c) * NHEADS + h) * HEADDIM * DSTATE;
        const __half* sP = g_prev + pb;
#pragma unroll
        for (int it = 0; it < 4; it++) {
            int v = tid + (it << 8);
            int r = v >> 4, ch = v & 15;
            cp16(sb + (Y_C_O + r * 68 + ch * 4) * 4, sC + (size_t)r * DSTATE + ch * 8);
            cp16(sb + (Y_PV_O + r * 68 + ch * 4) * 4, sP + (size_t)r * DSTATE + ch * 8);
        }
        asm volatile("cp.async.commit_group;" ::: "memory");
    }
    load_bx(0, 0);

    asm volatile("cp.async.wait_group 1;" ::: "memory");
    __syncthreads();

    float Yacc[2][2][4];
#pragma unroll
    for (int i = 0; i < 2; i++)
#pragma unroll
        for (int j = 0; j < 2; j++)
#pragma unroll
            for (int q = 0; q < 4; q++) Yacc[i][j][q] = 0.f;

    const int arow = warp_m * 32 + ((lane >> 3) & 1) * 8 + (lane & 7);
    const int akw  = (lane >> 4) << 2;
    const int brow = warp_n * 16 + ((lane >> 4) & 1) * 8 + (lane & 7);
    const int bkw  = ((lane >> 3) & 1) << 2;

#pragma unroll
    for (int kk = 0; kk < 8; kk++) {
        uint32_t a[2][4], bf[4];
#pragma unroll
        for (int mi = 0; mi < 2; mi++)
            ldsm4(a[mi], sb + (uint32_t)(Y_C_O + (arow + mi * 16) * 68 + kk * 8 + akw) * 4);
        ldsm4(bf, sb + (uint32_t)(Y_PV_O + brow * 68 + kk * 8 + bkw) * 4);
#pragma unroll
        for (int mi = 0; mi < 2; mi++) {
            mma_fp16(Yacc[mi][0], a[mi], bf);
            mma_fp16(Yacc[mi][1], a[mi], bf + 2);
        }
    }
#pragma unroll
    for (int mi = 0; mi < 2; mi++) {
        int r0 = l0 + warp_m * 32 + mi * 16 + (lane >> 2);
        float e0 = __expf(acs_s[r0]);
        float e1 = __expf(acs_s[r0 + 8]);
#pragma unroll
        for (int ni = 0; ni < 2; ni++) {
            Yacc[mi][ni][0] *= e0; Yacc[mi][ni][1] *= e0;
            Yacc[mi][ni][2] *= e1; Yacc[mi][ni][3] *= e1;
        }
    }

    for (int st = 0; st <= lt; st++) {
        if (st + 1 <= lt) {
            load_bx(st + 1, (st + 1) & 1);
            asm volatile("cp.async.wait_group 1;" ::: "memory");
        } else {
            asm volatile("cp.async.wait_group 0;" ::: "memory");
        }
        __syncthreads();

        const uint32_t bo = (st & 1) ? (uint32_t)Y_B1_O : (uint32_t)Y_B0_O;
        const uint32_t xo = (st & 1) ? (uint32_t)Y_X1_O : (uint32_t)Y_X0_O;
        int s0 = st * 64;

        float sacc[2][2][4];
#pragma unroll
        for (int i = 0; i < 2; i++)
#pragma unroll
            for (int j = 0; j < 2; j++)
#pragma unroll
                for (int q = 0; q < 4; q++) sacc[i][j][q] = 0.f;
#pragma unroll
        for (int kk = 0; kk < 8; kk++) {
            uint32_t a[2][4], bf[4];
#pragma unroll
            for (int mi = 0; mi < 2; mi++)
                ldsm4(a[mi], sb + (uint32_t)(Y_C_O + (arow + mi * 16) * 68 + kk * 8 + akw) * 4);
            ldsm4(bf, sb + (bo + brow * 68 + kk * 8 + bkw) * 4);
#pragma unroll
            for (int mi = 0; mi < 2; mi++) {
                mma_fp16(sacc[mi][0], a[mi], bf);
                mma_fp16(sacc[mi][1], a[mi], bf + 2);
            }
        }
#pragma unroll
        for (int mi = 0; mi < 2; mi++) {
            int rr0 = warp_m * 32 + mi * 16 + (lane >> 2);
            int lg0 = l0 + rr0, lg1 = lg0 + 8;
            float a0 = acs_s[lg0], a1 = acs_s[lg1];
#pragma unroll
            for (int ni = 0; ni < 2; ni++) {
                int ccc = warp_n * 16 + ni * 8 + 2 * (lane & 3);
                int sg = s0 + ccc;
                float as0 = acs_s[sg], as1 = acs_s[sg + 1];
                float v00 = (sg     <= lg0) ? sacc[mi][ni][0] * __expf(a0 - as0) : 0.f;
                float v01 = (sg + 1 <= lg0) ? sacc[mi][ni][1] * __expf(a0 - as1) : 0.f;
                float v10 = (sg     <= lg1) ? sacc[mi][ni][2] * __expf(a1 - as0) : 0.f;
                float v11 = (sg + 1 <= lg1) ? sacc[mi][ni][3] * __expf(a1 - as1) : 0.f;
                sw[Y_S_O + rr0 * 36 + (ccc >> 1)] =
                    packh2(__float2half_rn(v00), __float2half_rn(v01));
                sw[Y_S_O + (rr0 + 8) * 36 + (ccc >> 1)] =
                    packh2(__float2half_rn(v10), __float2half_rn(v11));
            }
        }
        __syncthreads();
#pragma unroll
        for (int kk = 0; kk < 4; kk++) {
            uint32_t a[2][4], bf[4];
#pragma unroll
            for (int mi = 0; mi < 2; mi++)
                ldsm4(a[mi], sb + (uint32_t)(Y_S_O + (arow + mi * 16) * 36 + kk * 8 + akw) * 4);
            ldsm4(bf, sb + (xo + brow * 36 + kk * 8 + bkw) * 4);
#pragma unroll
            for (int mi = 0; mi < 2; mi++) {
                mma_fp16(Yacc[mi][0], a[mi], bf);
                mma_fp16(Yacc[mi][1], a[mi], bf + 2);
            }
        }
    }

    // epilogue: + D*x_ssm, gate silu(z), fp16 store + row sumsq atomics
    float Dh = Dp[h];
#pragma unroll
    for (int mi = 0; mi < 2; mi++) {
#pragma unroll
        for (int q = 0; q < 2; q++) {
            int rr = warp_m * 32 + mi * 16 + (lane >> 2) + q * 8;
            int t = bt0 + l0 + rr;
            float local = 0.f;
#pragma unroll
            for (int ni = 0; ni < 2; ni++) {
                int pp = warp_n * 16 + ni * 8 + 2 * (lane & 3);
                float2 xs = __half22float2(*(const __half2*)(g_xs + (size_t)t * DINNER + h * HEADDIM + pp));
                float2 zz = *(const float2*)(g_zx + (size_t)t * D_IN_PROJ + h * HEADDIM + pp);
                float y0 = (Yacc[mi][ni][q * 2 + 0] + xs.x * Dh) * siluf(zz.x);
                float y1 = (Yacc[mi][ni][q * 2 + 1] + xs.y * Dh) * siluf(zz.y);
                *(__half2*)(g_ygh + (size_t)t * DINNER + h * HEADDIM + pp) = __floats2half2_rn(y0, y1);
                local += y0 * y0 + y1 * y1;
            }
            local += __shfl_xor_sync(0xFFFFFFFFu, local, 1);
            local += __shfl_xor_sync(0xFFFFFFFFu, local, 2);
            if ((lane & 3) == 0) atomicAdd(&g_ss[t], local);
        }
    }
}

// ---------------- RMSNorm scale pass (reads precomputed sumsq) -> fp16 ----------------
__global__ __launch_bounds__(256) void rmsnorm_kernel(const float* __restrict__ w)
{
    int row = blockIdx.x;
    const __half* y = g_ygh + (size_t)row * DINNER;
    __half* oh = g_ynh + (size_t)row * DINNER;
    int tid = threadIdx.x;
    float scale = rsqrtf(g_ss[row] / (float)DINNER + EPSV);
#pragma unroll
    for (int it = 0; it < 4; it++) {
        int i = it * 1024 + tid * 4;
        float2 v0 = __half22float2(*(const __half2*)(y + i));
        float2 v1 = __half22float2(*(const __half2*)(y + i + 2));
        float4 wv = *(const float4*)(w + i);
        __half2* hp = (__half2*)(oh + i);
        hp[0] = __floats2half2_rn(v0.x * scale * wv.x, v0.y * scale * wv.y);
        hp[1] = __floats2half2_rn(v1.x * scale * wv.z, v1.y * scale * wv.w);
    }
}

// ---------------- launch ----------------
extern "C" void kernel_launch(void* const* d_in, const int* in_sizes, int n_in,
                              void* d_out, int out_size)
{
    const float* x          = (const float*)d_in[0];
    const float* in_proj_w  = (const float*)d_in[1];
    const float* conv_w     = (const float*)d_in[2];
    const float* conv_b     = (const float*)d_in[3];
    const float* dt_bias    = (const float*)d_in[4];
    const float* A_log      = (const float*)d_in[5];
    const float* Dp         = (const float*)d_in[6];
    const float* norm_w     = (const float*)d_in[7];
    const float* out_proj_w = (const float*)d_in[8];
    float* out = (float*)d_out;

    float *zx_p = nullptr, *ss_p = nullptr;
    __half *xh_p, *wih_p, *ynh_p, *owh_p;
    cudaGetSymbolAddress((void**)&zx_p, g_zx);
    cudaGetSymbolAddress((void**)&ss_p, g_ss);
    cudaGetSymbolAddress((void**)&xh_p, g_xh);
    cudaGetSymbolAddress((void**)&wih_p, g_wih);
    cudaGetSymbolAddress((void**)&ynh_p, g_ynh);
    cudaGetSymbolAddress((void**)&owh_p, g_owh);

    static int gemm_grid = 0;
    if (gemm_grid == 0) {
        cudaFuncSetAttribute(gemm_hmma_fp16, cudaFuncAttributeMaxDynamicSharedMemorySize, GEMM1_SMEM);
        cudaFuncSetAttribute(states_hmma, cudaFuncAttributeMaxDynamicSharedMemorySize, S_SMEM_BYTES);
        cudaFuncSetAttribute(y_hmma, cudaFuncAttributeMaxDynamicSharedMemorySize, Y_SMEM_BYTES);
        int sms = 148, dev = 0;
        cudaGetDevice(&dev);
        cudaDeviceGetAttribute(&sms, cudaDevAttrMultiProcessorCount, dev);
        gemm_grid = 2 * sms;
    }

    const int M = B_SZ * SEQL; // 4096

    // 0) merged converts
    cvt_all<<<CVT_B1 + CVT_B2 + CVT_B3, 256>>>(x, in_proj_w, out_proj_w, xh_p, wih_p, owh_p);

    // 1) in_proj GEMM (persistent)
    {
        int nTiles = (DIP_PAD / 128) * (M / 128);
        gemm_hmma_fp16<<<min(gemm_grid, nTiles), 256, GEMM1_SMEM>>>(
            xh_p, wih_p, zx_p, M, D_IN_PROJ, DMODEL, DIP_PAD / 128);
    }

    // zero sumsq (needed before y_hmma; independent of steps 2-6)
    cudaMemsetAsync(ss_p, 0, B_SZ * SEQL * sizeof(float));

    // 2+3) conv+silu and dt softplus+cumsum, merged
    conv_dt_kernel<<<1024 + 17 * B_SZ * (SEQL / 256), 256>>>(conv_w, conv_b, dt_bias, A_log);

    // 4) SSM operand transposes, merged
    cvt_ssm_kernel<<<512 + (SEQL / 64) * NHEADS * B_SZ, 256>>>();

    // 5) states
    states_hmma<<<B_SZ * NCHUNK * NHEADS, 256, S_SMEM_BYTES>>>();

    // 6) recurrence
    prev_kernel<<<B_SZ * NHEADS, 1024>>>();

    // 7) Y + gate + sumsq
    y_hmma<<<B_SZ * NCHUNK * NHEADS * 4, 256, Y_SMEM_BYTES>>>(Dp);

    // 8) RMSNorm scale
    rmsnorm_kernel<<<B_SZ * SEQL, 256>>>(norm_w);

    // 9) out_proj GEMM (persistent)
    {
        int nTiles = (DMODEL / 128) * (M / 128);
        gemm_hmma_fp16<<<min(gemm_grid, nTiles), 256, GEMM1_SMEM>>>(
            ynh_p, owh_p, out, M, DMODEL, DINNER, DMODEL / 128);
    }

    (void)in_sizes; (void)n_in; (void)out_size;
}

// round 13
// speedup vs baseline: 1.0350x; 1.0350x over previous
#include <cuda_runtime.h>
#include <cuda_bf16.h>
#include <cuda_fp16.h>
#include <cstdint>
#include <cstring>

#define B_SZ 2
#define SEQL 2048
#define DMODEL 2048
#define DINNER 4096
#define DSTATE 128
#define HEADDIM 64
#define NHEADS 64
#define CHUNKL 256
#define NCHUNK 8
#define CONV_DIM 4352     // DINNER + 2*DSTATE
#define D_IN_PROJ 8512    // 2*DINNER + 2*DSTATE + NHEADS
#define DIP_PAD 8576      // 67*128
#define EPSV 1e-5f

// ---------------- scratch ----------------
__device__ float g_zx[B_SZ*SEQL*D_IN_PROJ];
__device__ float g_dt[B_SZ*SEQL*NHEADS];
__device__ float g_Acs[B_SZ*NHEADS*NCHUNK*CHUNKL];
__device__ float g_ss[B_SZ*SEQL];
// fp16 gemm operands
__device__ __half g_xh[B_SZ*SEQL*DMODEL];
__device__ __half g_wih[(size_t)DIP_PAD*DMODEL];
__device__ __half g_ynh[B_SZ*SEQL*DINNER];
__device__ __half g_owh[(size_t)DMODEL*DINNER];
// fp16 activations / SSM operands
__device__ __half g_xs[B_SZ*SEQL*DINNER];
__device__ __half g_B[B_SZ*SEQL*DSTATE];
__device__ __half g_C[B_SZ*SEQL*DSTATE];
__device__ __half g_BT[B_SZ*DSTATE*SEQL];
__device__ __half g_XdT[(size_t)B_SZ*NHEADS*HEADDIM*SEQL];
__device__ __half g_XdecT[(size_t)B_SZ*NHEADS*HEADDIM*SEQL];
__device__ __half g_statesh[(size_t)B_SZ*NCHUNK*NHEADS*HEADDIM*DSTATE];
__device__ __half g_prev[(size_t)B_SZ*NCHUNK*NHEADS*HEADDIM*DSTATE];
__device__ __half g_ygh[B_SZ*SEQL*DINNER];

__device__ __forceinline__ float siluf(float a) { return a / (1.f + expf(-a)); }

// ================= common HMMA helpers =================
__device__ __forceinline__ void mma_fp16(float* c, const uint32_t* a, const uint32_t* b) {
    asm volatile(
        "mma.sync.aligned.m16n8k16.row.col.f32.f16.f16.f32 "
        "{%0,%1,%2,%3}, {%4,%5,%6,%7}, {%8,%9}, {%0,%1,%2,%3};"
        : "+f"(c[0]), "+f"(c[1]), "+f"(c[2]), "+f"(c[3])
        : "r"(a[0]), "r"(a[1]), "r"(a[2]), "r"(a[3]), "r"(b[0]), "r"(b[1]));
}
__device__ __forceinline__ void ldsm4(uint32_t* r, uint32_t addr) {
    asm volatile("ldmatrix.sync.aligned.m8n8.x4.shared.b16 {%0,%1,%2,%3}, [%4];"
        : "=r"(r[0]), "=r"(r[1]), "=r"(r[2]), "=r"(r[3]) : "r"(addr));
}
__device__ __forceinline__ void cp16(uint32_t dst, const void* src) {
    asm volatile("cp.async.cg.shared.global [%0], [%1], 16;" :: "r"(dst), "l"(src));
}
__device__ __forceinline__ uint32_t smem_u32(const void* p) {
    uint32_t a;
    asm("{ .reg .u64 t; cvta.to.shared.u64 t, %1; cvt.u32.u64 %0, t; }" : "=r"(a) : "l"(p));
    return a;
}
__device__ __forceinline__ uint32_t packh2(__half a, __half b) {
    __half2 h = __halves2half2(a, b);
    uint32_t u; memcpy(&u, &h, 4); return u;
}

// ================= fp16 HMMA GEMM, BK=64, 3 stages (round-11 proven version) =================
#define OPW64 4096
#define STG64 (2 * OPW64)
#define GEMM1_SMEM (3 * STG64 * 4)        // 98304 B

__device__ __forceinline__ void load_op64(uint32_t sbase_b, const __half* g, int ldk, int tid) {
#pragma unroll
    for (int it = 0; it < 4; it++) {
        int v = tid + (it << 8);
        int r = v >> 3, ch = v & 7;
        int sch = ch ^ (r & 7);
        cp16(sbase_b + (r * 32 + (sch << 2)) * 4, g + (size_t)r * ldk + (ch << 3));
    }
}

__global__ __launch_bounds__(256, 2) void gemm_hmma_fp16(
    const __half* __restrict__ A, const __half* __restrict__ B,
    float* __restrict__ C, int M, int Nreal, int K)
{
    extern __shared__ uint32_t sw[];
    const uint32_t sb = smem_u32(sw);
    const int tid = threadIdx.x, wid = tid >> 5, lane = tid & 31;
    const int warp_m = wid & 1, warp_n = wid >> 1;
    const int m0 = blockIdx.y << 7, n0 = blockIdx.x << 7;
    const int KT = K >> 6;

    const __half* Ab = A + (size_t)m0 * K;
    const __half* Bb = B + (size_t)n0 * K;

    float acc[4][4][4];
#pragma unroll
    for (int i = 0; i < 4; i++)
#pragma unroll
        for (int j = 0; j < 4; j++)
#pragma unroll
            for (int q = 0; q < 4; q++) acc[i][j][q] = 0.f;

#pragma unroll
    for (int s = 0; s < 2; s++) {
        int koff = s << 6;
        load_op64(sb + (s * STG64) * 4, Ab + koff, K, tid);
        load_op64(sb + (s * STG64 + OPW64) * 4, Bb + koff, K, tid);
        asm volatile("cp.async.commit_group;" ::: "memory");
    }

    const int rowA = warp_m * 64 + ((lane >> 3) & 1) * 8 + (lane & 7);
    const int cA0  = lane >> 4;
    const int rowB = warp_n * 32 + ((lane >> 4) & 1) * 8 + (lane & 7);
    const int cB0  = (lane >> 3) & 1;

    int buf = 0;
    for (int kt = 0; kt < KT; kt++) {
        if (kt + 1 < KT) asm volatile("cp.async.wait_group 1;" ::: "memory");
        else             asm volatile("cp.async.wait_group 0;" ::: "memory");
        __syncthreads();
        if (kt + 2 < KT) {
            int s = buf + 2; if (s >= 3) s -= 3;
            int koff = (kt + 2) << 6;
            load_op64(sb + (s * STG64) * 4, Ab + koff, K, tid);
            load_op64(sb + (s * STG64 + OPW64) * 4, Bb + koff, K, tid);
            asm volatile("cp.async.commit_group;" ::: "memory");
        }

        const uint32_t sA = sb + (uint32_t)buf * STG64 * 4u;
        const uint32_t sB = sA + OPW64 * 4u;

#pragma unroll
        for (int kk = 0; kk < 4; kk++) {
            uint32_t a[4][4];
#pragma unroll
            for (int mi = 0; mi < 4; mi++) {
                int r = rowA + mi * 16;
                uint32_t off = (r * 32 + ((((kk << 1) + cA0) ^ (r & 7)) << 2)) * 4u;
                ldsm4(a[mi], sA + off);
            }
#pragma unroll
            for (int np = 0; np < 2; np++) {
                int r = rowB + np * 16;
                uint32_t boff = (r * 32 + ((((kk << 1) + cB0) ^ (r & 7)) << 2)) * 4u;
                uint32_t b[4];
                ldsm4(b, sB + boff);
#pragma unroll
                for (int mi = 0; mi < 4; mi++) {
                    mma_fp16(acc[mi][2 * np], a[mi], b);
                    mma_fp16(acc[mi][2 * np + 1], a[mi], b + 2);
                }
            }
        }
        buf++; if (buf == 3) buf = 0;
    }

#pragma unroll
    for (int mi = 0; mi < 4; mi++) {
        int rg0 = m0 + warp_m * 64 + mi * 16 + (lane >> 2);
#pragma unroll
        for (int ni = 0; ni < 4; ni++) {
            int cg = n0 + warp_n * 32 + ni * 8 + ((lane & 3) << 1);
            if (cg < Nreal) {
                *(float2*)(C + (size_t)rg0 * Nreal + cg) =
                    make_float2(acc[mi][ni][0], acc[mi][ni][1]);
                *(float2*)(C + (size_t)(rg0 + 8) * Nreal + cg) =
                    make_float2(acc[mi][ni][2], acc[mi][ni][3]);
            }
        }
    }
}

// ---------------- merged fp32 -> fp16 converts ----------------
#define CVT_N1 ((long)B_SZ*SEQL*DMODEL)
#define CVT_NS2 ((long)D_IN_PROJ*DMODEL)
#define CVT_NT2 ((long)DIP_PAD*DMODEL)
#define CVT_N3 ((long)DMODEL*DINNER)
#define CVT_B1 ((unsigned)(CVT_N1/4/256))
#define CVT_B2 ((unsigned)(CVT_NT2/4/256))
#define CVT_B3 ((unsigned)(CVT_N3/4/256))

__global__ void cvt_all(const float* __restrict__ x, const float* __restrict__ wi,
                        const float* __restrict__ wo,
                        __half* __restrict__ xh, __half* __restrict__ wih,
                        __half* __restrict__ owh)
{
    unsigned bid = blockIdx.x;
    const float* src; __half* dst; long i, n_src;
    if (bid < CVT_B1) {
        i = ((long)bid * 256 + threadIdx.x) * 4; src = x; dst = xh; n_src = CVT_N1;
    } else if (bid < CVT_B1 + CVT_B2) {
        i = ((long)(bid - CVT_B1) * 256 + threadIdx.x) * 4; src = wi; dst = wih; n_src = CVT_NS2;
    } else {
        i = ((long)(bid - CVT_B1 - CVT_B2) * 256 + threadIdx.x) * 4; src = wo; dst = owh; n_src = CVT_N3;
    }
    float4 v = (i < n_src) ? *(const float4*)(src + i) : make_float4(0.f, 0.f, 0.f, 0.f);
    __half2* dp = (__half2*)(dst + i);
    dp[0] = __floats2half2_rn(v.x, v.y);
    dp[1] = __floats2half2_rn(v.z, v.w);
}

// ---------------- merged conv+silu (fp16 out) and dt softplus+cumsum ----------------
__global__ void conv_dt_kernel(const float* __restrict__ conv_w,
                               const float* __restrict__ conv_b,
                               const float* __restrict__ dt_bias,
                               const float* __restrict__ A_log)
{
    __shared__ float s[CHUNKL];
    if (blockIdx.x < 1024) {
        int idx = blockIdx.x;
        int c = idx % NCHUNK; idx /= NCHUNK;
        int h = idx % NHEADS;
        int b = idx / NHEADS;
        int l = threadIdx.x;
        int t = c * CHUNKL + l;
        float raw = g_zx[(size_t)(b * SEQL + t) * D_IN_PROJ + DINNER + CONV_DIM + h];
        float xv = raw + dt_bias[h];
        float dt = (xv > 20.f) ? xv : log1pf(expf(xv));
        g_dt[(b * SEQL + t) * NHEADS + h] = dt;
        float dA = dt * (-expf(A_log[h]));
        s[l] = dA;
        __syncthreads();
        for (int off = 1; off < CHUNKL; off <<= 1) {
            float v = (l >= off) ? s[l - off] : 0.f;
            __syncthreads();
            s[l] += v;
            __syncthreads();
        }
        g_Acs[((b * NHEADS + h) * NCHUNK + c) * CHUNKL + l] = s[l];
    } else {
        int bid2 = blockIdx.x - 1024;
        int chunk = bid2 % 17; bid2 /= 17;
        int b = bid2 & 1;
        int t0 = (bid2 >> 1) * 256;
        int c = chunk * 256 + threadIdx.x;
        float w0 = conv_w[c * 4 + 0], w1 = conv_w[c * 4 + 1];
        float w2 = conv_w[c * 4 + 2], w3 = conv_w[c * 4 + 3];
        float bias = conv_b[c];
        const float* src = g_zx + (size_t)b * SEQL * D_IN_PROJ + DINNER + c;
        __half* dst; int stride;
        if (c < DINNER) {
            dst = g_xs + (size_t)b * SEQL * DINNER + c;           stride = DINNER;
        } else if (c < DINNER + DSTATE) {
            dst = g_B + (size_t)b * SEQL * DSTATE + (c - DINNER); stride = DSTATE;
        } else {
            dst = g_C + (size_t)b * SEQL * DSTATE + (c - DINNER - DSTATE); stride = DSTATE;
        }
        dst += (size_t)t0 * stride;
        float x0 = (t0 >= 3) ? src[(size_t)(t0 - 3) * D_IN_PROJ] : 0.f;
        float x1 = (t0 >= 2) ? src[(size_t)(t0 - 2) * D_IN_PROJ] : 0.f;
        float x2 = (t0 >= 1) ? src[(size_t)(t0 - 1) * D_IN_PROJ] : 0.f;
        for (int t = 0; t < 256; t++) {
            float x3 = src[(size_t)(t0 + t) * D_IN_PROJ];
            float a = bias + w0 * x0 + w1 * x1 + w2 * x2 + w3 * x3;
            dst[(size_t)t * stride] = __float2half_rn(siluf(a));
            x0 = x1; x1 = x2; x2 = x3;
        }
    }
}

// ---------------- merged SSM operand transposes ----------------
__global__ void cvt_ssm_kernel()
{
    __shared__ float xs[64][65];
    __shared__ float dts[64], dec[64];
    __shared__ __half btile[32][34];
    int tid = threadIdx.x;
    if (blockIdx.x < 512) {
        int i = blockIdx.x;
        int t0 = (i & 63) * 32; i >>= 6;
        int n0 = (i & 3) * 32;
        int b = i >> 2;
#pragma unroll
        for (int it = 0; it < 4; it++) {
            int v = tid + it * 256;
            int t = v >> 5, n = v & 31;
            btile[t][n] = g_B[(size_t)(b * SEQL + t0 + t) * DSTATE + n0 + n];
        }
        __syncthreads();
#pragma unroll
        for (int it = 0; it < 2; it++) {
            int v = tid + it * 256;
            int n = v >> 4, tc = (v & 15) << 1;
            size_t o = (size_t)(b * DSTATE + n0 + n) * SEQL + t0 + tc;
            *(__half2*)(g_BT + o) = __halves2half2(btile[tc][n], btile[tc + 1][n]);
        }
    } else {
        int j = blockIdx.x - 512;
        int tt = j & 31; j >>= 5;
        int h = j & 63;
        int b = j >> 6;
        int t0 = tt * 64;
        int c = t0 >> 8;
        const float* acs = g_Acs + ((b * NHEADS + h) * NCHUNK + c) * CHUNKL;
        if (tid < 64) {
            int tl = (t0 & 255) + tid;
            dts[tid] = g_dt[(size_t)(b * SEQL + t0 + tid) * NHEADS + h];
            dec[tid] = __expf(acs[CHUNKL - 1] - acs[tl]);
        }
#pragma unroll
        for (int it = 0; it < 16; it++) {
            int v = tid + it * 256;
            int t = v >> 6, p = v & 63;
            xs[t][p] = __half2float(g_xs[(size_t)(b * SEQL + t0 + t) * DINNER + h * HEADDIM + p]);
        }
        __syncthreads();
#pragma unroll
        for (int it = 0; it < 8; it++) {
            int v = tid + it * 256;
            int p = v >> 5, tc = (v & 31) << 1;
            size_t o = ((size_t)((b * NHEADS + h) * HEADDIM) + p) * SEQL + t0 + tc;
            float x0 = xs[tc][p] * dts[tc];
            float x1 = xs[tc + 1][p] * dts[tc + 1];
            *(__half2*)(g_XdT + o)   = __floats2half2_rn(x0, x1);
            *(__half2*)(g_XdecT + o) = __floats2half2_rn(x0 * dec[tc], x1 * dec[tc + 1]);
        }
    }
}

// ---------------- states (single fp16 HMMA) -> fp16 output ----------------
#define S_A_O 0
#define S_B_O 2048
#define S_STG 6144
#define S_SMEM_BYTES (2 * S_STG * 4)

__global__ __launch_bounds__(256, 2) void states_hmma()
{
    extern __shared__ uint32_t sw[];
    const uint32_t sb = smem_u32(sw);
    int bid = blockIdx.x;
    int h = bid & 63, cc = (bid >> 6) & 7, b = bid >> 9;
    int tid = threadIdx.x, wid = tid >> 5, lane = tid & 31;
    int warp_m = wid >> 2, warp_n = wid & 3;
    const __half* A = g_XdecT + (size_t)((b * NHEADS + h) * HEADDIM) * SEQL + cc * CHUNKL;
    const __half* B = g_BT + (size_t)(b * DSTATE) * SEQL + cc * CHUNKL;

    float acc[2][4][4];
#pragma unroll
    for (int i = 0; i < 2; i++)
#pragma unroll
        for (int j = 0; j < 4; j++)
#pragma unroll
            for (int q = 0; q < 4; q++) acc[i][j][q] = 0.f;

    auto load_stage = [&](int kc, int buf) {
        uint32_t base = (uint32_t)buf * S_STG;
        int koff = kc * 64;
#pragma unroll
        for (int it = 0; it < 2; it++) {
            int v = tid + (it << 8);
            int r = v >> 3, ch = v & 7;
            int sch = ch ^ (r & 7);
            cp16(sb + (base + S_A_O + r * 32 + sch * 4) * 4, A + (size_t)r * SEQL + koff + ch * 8);
        }
#pragma unroll
        for (int it = 0; it < 4; it++) {
            int v = tid + (it << 8);
            int r = v >> 3, ch = v & 7;
            int sch = ch ^ (r & 7);
            cp16(sb + (base + S_B_O + r * 32 + sch * 4) * 4, B + (size_t)r * SEQL + koff + ch * 8);
        }
        asm volatile("cp.async.commit_group;" ::: "memory");
    };

    load_stage(0, 0);
    load_stage(1, 1);

    const int arow = warp_m * 32 + ((lane >> 3) & 1) * 8 + (lane & 7);
    const int cA0 = lane >> 4;
    const int brl = ((lane >> 4) & 1) * 8 + (lane & 7);
    const int cB0 = (lane >> 3) & 1;

    for (int kc = 0; kc < 4; kc++) {
        if (kc < 3) asm volatile("cp.async.wait_group 1;" ::: "memory");
        else        asm volatile("cp.async.wait_group 0;" ::: "memory");
        __syncthreads();
        uint32_t base = (uint32_t)(kc & 1) * S_STG;
#pragma unroll
        for (int kk = 0; kk < 4; kk++) {
            uint32_t a[2][4];
#pragma unroll
            for (int mi = 0; mi < 2; mi++) {
                int r = arow + mi * 16;
                uint32_t w = base + S_A_O + r * 32 + ((((kk << 1) + cA0) ^ (r & 7)) << 2);
                ldsm4(a[mi], sb + w * 4);
            }
#pragma unroll
            for (int np = 0; np < 2; np++) {
                int rb = warp_n * 32 + np * 16 + brl;
                uint32_t w = base + S_B_O + rb * 32 + ((((kk << 1) + cB0) ^ (rb & 7)) << 2);
                uint32_t bf[4];
                ldsm4(bf, sb + w * 4);
#pragma unroll
                for (int mi = 0; mi < 2; mi++) {
                    mma_fp16(acc[mi][2 * np], a[mi], bf);
                    mma_fp16(acc[mi][2 * np + 1], a[mi], bf + 2);
                }
            }
        }
        __syncthreads();
        if (kc + 2 < 4) load_stage(kc + 2, kc & 1);
    }

    __half* out = g_statesh + (size_t)((b * NCHUNK + cc) * NHEADS + h) * HEADDIM * DSTATE;
#pragma unroll
    for (int mi = 0; mi < 2; mi++) {
        int r0 = warp_m * 32 + mi * 16 + (lane >> 2);
#pragma unroll
        for (int ni = 0; ni < 4; ni++) {
            int col = warp_n * 32 + ni * 8 + 2 * (lane & 3);
            *(__half2*)(out + (size_t)r0 * DSTATE + col) =
                __floats2half2_rn(acc[mi][ni][0], acc[mi][ni][1]);
            *(__half2*)(out + (size_t)(r0 + 8) * DSTATE + col) =
                __floats2half2_rn(acc[mi][ni][2], acc[mi][ni][3]);
        }
    }
}

// ---------------- inter-chunk recurrence ----------------
__global__ __launch_bounds__(1024) void prev_kernel()
{
    int b = blockIdx.x >> 6;
    int h = blockIdx.x & 63;
    int tid = threadIdx.x;
    float P[8];
#pragma unroll
    for (int i = 0; i < 8; i++) P[i] = 0.f;
    for (int c = 0; c < NCHUNK; c++) {
        float decay = __expf(g_Acs[((b * NHEADS + h) * NCHUNK + c) * CHUNKL + CHUNKL - 1]);
        size_t base = (size_t)((b * NCHUNK + c) * NHEADS + h) * HEADDIM * DSTATE;
#pragma unroll
        for (int i = 0; i < 8; i++) {
            int e = i * 1024 + tid;
            float v = P[i];
            g_prev[base + e] = __float2half_rn(v);
            P[i] = v * decay + __half2float(g_statesh[base + e]);
        }
    }
}

// ---------------- Y via single fp16 HMMA -> fp16 out + fused sumsq ----------------
#define Y_ACS_O 0
#define Y_C_O 256
#define Y_PV_O (Y_C_O + 4352)
#define Y_B0_O (Y_PV_O + 4352)
#define Y_B1_O (Y_B0_O + 4352)
#define Y_X0_O (Y_B1_O + 4352)
#define Y_X1_O (Y_X0_O + 2304)
#define Y_S_O  (Y_X1_O + 2304)
#define Y_SMEM_BYTES ((Y_S_O + 2304) * 4)

__global__ __launch_bounds__(256, 2) void y_hmma(const float* __restrict__ Dp)
{
    extern __shared__ uint32_t sw[];
    const uint32_t sb = smem_u32(sw);
    float* acs_s = (float*)(sw + Y_ACS_O);
    int bid = blockIdx.x;
    int lt = bid & 3, h = (bid >> 2) & 63, c = (bid >> 8) & 7, b = bid >> 11;
    int tid = threadIdx.x, wid = tid >> 5, lane = tid & 31;
    int warp_m = wid >> 2, warp_n = wid & 3;
    int l0 = lt * 64;
    const int bt0 = b * SEQL + c * CHUNKL;

    acs_s[tid] = g_Acs[((b * NHEADS + h) * NCHUNK + c) * CHUNKL + tid];

    const __half* gB = g_B + (size_t)bt0 * DSTATE;
    const __half* gX = g_XdT + (size_t)((b * NHEADS + h) * HEADDIM) * SEQL + c * CHUNKL;

    auto load_bx = [&](int st, int pbuf) {
        const __half* Bp = gB + (size_t)(st * 64) * DSTATE;
        const __half* Xp = gX + st * 64;
        uint32_t bo = pbuf ? (uint32_t)Y_B1_O : (uint32_t)Y_B0_O;
        uint32_t xo = pbuf ? (uint32_t)Y_X1_O : (uint32_t)Y_X0_O;
#pragma unroll
        for (int it = 0; it < 4; it++) {
            int v = tid + (it << 8);
            int r = v >> 4, ch = v & 15;
            cp16(sb + (bo + r * 68 + ch * 4) * 4, Bp + (size_t)r * DSTATE + ch * 8);
        }
#pragma unroll
        for (int it = 0; it < 2; it++) {
            int v = tid + (it << 8);
            int r = v >> 3, ch = v & 7;
            cp16(sb + (xo + r * 36 + ch * 4) * 4, Xp + (size_t)r * SEQL + ch * 8);
        }
        asm volatile("cp.async.commit_group;" ::: "memory");
    };

    {
        const __half* sC = g_C + (size_t)(bt0 + l0) * DSTATE;
        size_t pb = (size_t)((b * NCHUNK + c) * NHEADS + h) * HEADDIM * DSTATE;
        const __half* sP = g_prev + pb;
#pragma unroll
        for (int it = 0; it < 4; it++) {
            int v = tid + (it << 8);
            int r = v >> 4, ch = v & 15;
            cp16(sb + (Y_C_O + r * 68 + ch * 4) * 4, sC + (size_t)r * DSTATE + ch * 8);
            cp16(sb + (Y_PV_O + r * 68 + ch * 4) * 4, sP + (size_t)r * DSTATE + ch * 8);
        }
        asm volatile("cp.async.commit_group;" ::: "memory");
    }
    load_bx(0, 0);

    asm volatile("cp.async.wait_group 1;" ::: "memory");
    __syncthreads();

    float Yacc[2][2][4];
#pragma unroll
    for (int i = 0; i < 2; i++)
#pragma unroll
        for (int j = 0; j < 2; j++)
#pragma unroll
            for (int q = 0; q < 4; q++) Yacc[i][j][q] = 0.f;

    const int arow = warp_m * 32 + ((lane >> 3) & 1) * 8 + (lane & 7);
    const int akw  = (lane >> 4) << 2;
    const int brow = warp_n * 16 + ((lane >> 4) & 1) * 8 + (lane & 7);
    const int bkw  = ((lane >> 3) & 1) << 2;

#pragma unroll
    for (int kk = 0; kk < 8; kk++) {
        uint32_t a[2][4], bf[4];
#pragma unroll
        for (int mi = 0; mi < 2; mi++)
            ldsm4(a[mi], sb + (uint32_t)(Y_C_O + (arow + mi * 16) * 68 + kk * 8 + akw) * 4);
        ldsm4(bf, sb + (uint32_t)(Y_PV_O + brow * 68 + kk * 8 + bkw) * 4);
#pragma unroll
        for (int mi = 0; mi < 2; mi++) {
            mma_fp16(Yacc[mi][0], a[mi], bf);
            mma_fp16(Yacc[mi][1], a[mi], bf + 2);
        }
    }
#pragma unroll
    for (int mi = 0; mi < 2; mi++) {
        int r0 = l0 + warp_m * 32 + mi * 16 + (lane >> 2);
        float e0 = __expf(acs_s[r0]);
        float e1 = __expf(acs_s[r0 + 8]);
#pragma unroll
        for (int ni = 0; ni < 2; ni++) {
            Yacc[mi][ni][0] *= e0; Yacc[mi][ni][1] *= e0;
            Yacc[mi][ni][2] *= e1; Yacc[mi][ni][3] *= e1;
        }
    }

    for (int st = 0; st <= lt; st++) {
        if (st + 1 <= lt) {
            load_bx(st + 1, (st + 1) & 1);
            asm volatile("cp.async.wait_group 1;" ::: "memory");
        } else {
            asm volatile("cp.async.wait_group 0;" ::: "memory");
        }
        __syncthreads();

        const uint32_t bo = (st & 1) ? (uint32_t)Y_B1_O : (uint32_t)Y_B0_O;
        const uint32_t xo = (st & 1) ? (uint32_t)Y_X1_O : (uint32_t)Y_X0_O;
        int s0 = st * 64;

        float sacc[2][2][4];
#pragma unroll
        for (int i = 0; i < 2; i++)
#pragma unroll
            for (int j = 0; j < 2; j++)
#pragma unroll
                for (int q = 0; q < 4; q++) sacc[i][j][q] = 0.f;
#pragma unroll
        for (int kk = 0; kk < 8; kk++) {
            uint32_t a[2][4], bf[4];
#pragma unroll
            for (int mi = 0; mi < 2; mi++)
                ldsm4(a[mi], sb + (uint32_t)(Y_C_O + (arow + mi * 16) * 68 + kk * 8 + akw) * 4);
            ldsm4(bf, sb + (bo + brow * 68 + kk * 8 + bkw) * 4);
#pragma unroll
            for (int mi = 0; mi < 2; mi++) {
                mma_fp16(sacc[mi][0], a[mi], bf);
                mma_fp16(sacc[mi][1], a[mi], bf + 2);
            }
        }
#pragma unroll
        for (int mi = 0; mi < 2; mi++) {
            int rr0 = warp_m * 32 + mi * 16 + (lane >> 2);
            int lg0 = l0 + rr0, lg1 = lg0 + 8;
            float a0 = acs_s[lg0], a1 = acs_s[lg1];
#pragma unroll
            for (int ni = 0; ni < 2; ni++) {
                int ccc = warp_n * 16 + ni * 8 + 2 * (lane & 3);
                int sg = s0 + ccc;
                float as0 = acs_s[sg], as1 = acs_s[sg + 1];
                float v00 = (sg     <= lg0) ? sacc[mi][ni][0] * __expf(a0 - as0) : 0.f;
                float v01 = (sg + 1 <= lg0) ? sacc[mi][ni][1] * __expf(a0 - as1) : 0.f;
                float v10 = (sg     <= lg1) ? sacc[mi][ni][2] * __expf(a1 - as0) : 0.f;
                float v11 = (sg + 1 <= lg1) ? sacc[mi][ni][3] * __expf(a1 - as1) : 0.f;
                sw[Y_S_O + rr0 * 36 + (ccc >> 1)] =
                    packh2(__float2half_rn(v00), __float2half_rn(v01));
                sw[Y_S_O + (rr0 + 8) * 36 + (ccc >> 1)] =
                    packh2(__float2half_rn(v10), __float2half_rn(v11));
            }
        }
        __syncthreads();
#pragma unroll
        for (int kk = 0; kk < 4; kk++) {
            uint32_t a[2][4], bf[4];
#pragma unroll
            for (int mi = 0; mi < 2; mi++)
                ldsm4(a[mi], sb + (uint32_t)(Y_S_O + (arow + mi * 16) * 36 + kk * 8 + akw) * 4);
            ldsm4(bf, sb + (xo + brow * 36 + kk * 8 + bkw) * 4);
#pragma unroll
            for (int mi = 0; mi < 2; mi++) {
                mma_fp16(Yacc[mi][0], a[mi], bf);
                mma_fp16(Yacc[mi][1], a[mi], bf + 2);
            }
        }
    }

    // epilogue: + D*x_ssm, gate silu(z), fp16 store + row sumsq atomics
    float Dh = Dp[h];
#pragma unroll
    for (int mi = 0; mi < 2; mi++) {
#pragma unroll
        for (int q = 0; q < 2; q++) {
            int rr = warp_m * 32 + mi * 16 + (lane >> 2) + q * 8;
            int t = bt0 + l0 + rr;
            float local = 0.f;
#pragma unroll
            for (int ni = 0; ni < 2; ni++) {
                int pp = warp_n * 16 + ni * 8 + 2 * (lane & 3);
                float2 xs = __half22float2(*(const __half2*)(g_xs + (size_t)t * DINNER + h * HEADDIM + pp));
                float2 zz = *(const float2*)(g_zx + (size_t)t * D_IN_PROJ + h * HEADDIM + pp);
                float y0 = (Yacc[mi][ni][q * 2 + 0] + xs.x * Dh) * siluf(zz.x);
                float y1 = (Yacc[mi][ni][q * 2 + 1] + xs.y * Dh) * siluf(zz.y);
                *(__half2*)(g_ygh + (size_t)t * DINNER + h * HEADDIM + pp) = __floats2half2_rn(y0, y1);
                local += y0 * y0 + y1 * y1;
            }
            local += __shfl_xor_sync(0xFFFFFFFFu, local, 1);
            local += __shfl_xor_sync(0xFFFFFFFFu, local, 2);
            if ((lane & 3) == 0) atomicAdd(&g_ss[t], local);
        }
    }
}

// ---------------- RMSNorm scale pass -> fp16 ----------------
__global__ __launch_bounds__(256) void rmsnorm_kernel(const float* __restrict__ w)
{
    int row = blockIdx.x;
    const __half* y = g_ygh + (size_t)row * DINNER;
    __half* oh = g_ynh + (size_t)row * DINNER;
    int tid = threadIdx.x;
    float scale = rsqrtf(g_ss[row] / (float)DINNER + EPSV);
#pragma unroll
    for (int it = 0; it < 4; it++) {
        int i = it * 1024 + tid * 4;
        float2 v0 = __half22float2(*(const __half2*)(y + i));
        float2 v1 = __half22float2(*(const __half2*)(y + i + 2));
        float4 wv = *(const float4*)(w + i);
        __half2* hp = (__half2*)(oh + i);
        hp[0] = __floats2half2_rn(v0.x * scale * wv.x, v0.y * scale * wv.y);
        hp[1] = __floats2half2_rn(v1.x * scale * wv.z, v1.y * scale * wv.w);
    }
}

// ---------------- launch ----------------
extern "C" void kernel_launch(void* const* d_in, const int* in_sizes, int n_in,
                              void* d_out, int out_size)
{
    const float* x          = (const float*)d_in[0];
    const float* in_proj_w  = (const float*)d_in[1];
    const float* conv_w     = (const float*)d_in[2];
    const float* conv_b     = (const float*)d_in[3];
    const float* dt_bias    = (const float*)d_in[4];
    const float* A_log      = (const float*)d_in[5];
    const float* Dp         = (const float*)d_in[6];
    const float* norm_w     = (const float*)d_in[7];
    const float* out_proj_w = (const float*)d_in[8];
    float* out = (float*)d_out;

    float *zx_p = nullptr, *ss_p = nullptr;
    __half *xh_p, *wih_p, *ynh_p, *owh_p;
    cudaGetSymbolAddress((void**)&zx_p, g_zx);
    cudaGetSymbolAddress((void**)&ss_p, g_ss);
    cudaGetSymbolAddress((void**)&xh_p, g_xh);
    cudaGetSymbolAddress((void**)&wih_p, g_wih);
    cudaGetSymbolAddress((void**)&ynh_p, g_ynh);
    cudaGetSymbolAddress((void**)&owh_p, g_owh);

    static bool attr_set = false;
    if (!attr_set) {
        cudaFuncSetAttribute(gemm_hmma_fp16, cudaFuncAttributeMaxDynamicSharedMemorySize, GEMM1_SMEM);
        cudaFuncSetAttribute(states_hmma, cudaFuncAttributeMaxDynamicSharedMemorySize, S_SMEM_BYTES);
        cudaFuncSetAttribute(y_hmma, cudaFuncAttributeMaxDynamicSharedMemorySize, Y_SMEM_BYTES);
        attr_set = true;
    }

    const int M = B_SZ * SEQL; // 4096

    // 0) merged converts
    cvt_all<<<CVT_B1 + CVT_B2 + CVT_B3, 256>>>(x, in_proj_w, out_proj_w, xh_p, wih_p, owh_p);

    // 1) in_proj GEMM (non-persistent, proven round-11 version)
    gemm_hmma_fp16<<<dim3(DIP_PAD / 128, M / 128), 256, GEMM1_SMEM>>>(
        xh_p, wih_p, zx_p, M, D_IN_PROJ, DMODEL);

    // zero sumsq for y_hmma accumulation
    cudaMemsetAsync(ss_p, 0, B_SZ * SEQL * sizeof(float));

    // 2+3) conv+silu and dt softplus+cumsum, merged
    conv_dt_kernel<<<1024 + 17 * B_SZ * (SEQL / 256), 256>>>(conv_w, conv_b, dt_bias, A_log);

    // 4) SSM operand transposes, merged
    cvt_ssm_kernel<<<512 + (SEQL / 64) * NHEADS * B_SZ, 256>>>();

    // 5) states
    states_hmma<<<B_SZ * NCHUNK * NHEADS, 256, S_SMEM_BYTES>>>();

    // 6) recurrence
    prev_kernel<<<B_SZ * NHEADS, 1024>>>();

    // 7) Y + gate + sumsq
    y_hmma<<<B_SZ * NCHUNK * NHEADS * 4, 256, Y_SMEM_BYTES>>>(Dp);

    // 8) RMSNorm scale
    rmsnorm_kernel<<<B_SZ * SEQL, 256>>>(norm_w);

    // 9) out_proj GEMM (non-persistent)
    gemm_hmma_fp16<<<dim3(DMODEL / 128, M / 128), 256, GEMM1_SMEM>>>(
        ynh_p, owh_p, out, M, DMODEL, DINNER);

    (void)in_sizes; (void)n_in; (void)out_size;
}

// round 14
// speedup vs baseline: 1.0535x; 1.0179x over previous
#include <cuda_runtime.h>
#include <cuda_bf16.h>
#include <cuda_fp16.h>
#include <cstdint>
#include <cstring>

#define B_SZ 2
#define SEQL 2048
#define DMODEL 2048
#define DINNER 4096
#define DSTATE 128
#define HEADDIM 64
#define NHEADS 64
#define CHUNKL 256
#define NCHUNK 8
#define CONV_DIM 4352     // DINNER + 2*DSTATE
#define D_IN_PROJ 8512    // 2*DINNER + 2*DSTATE + NHEADS
#define DIP_PAD 8576      // 67*128
#define DT_COL0 (DINNER + CONV_DIM)      // 8448
#define EPSV 1e-5f

// ---------------- scratch ----------------
__device__ float g_dtraw[B_SZ*SEQL*NHEADS];
__device__ float g_dt[B_SZ*SEQL*NHEADS];
__device__ float g_Acs[B_SZ*NHEADS*NCHUNK*CHUNKL];
__device__ float g_ss[B_SZ*SEQL];
// fp16 gemm operands / activations
__device__ __half g_zxh[(size_t)B_SZ*SEQL*D_IN_PROJ];
__device__ __half g_xh[B_SZ*SEQL*DMODEL];
__device__ __half g_wih[(size_t)DIP_PAD*DMODEL];
__device__ __half g_ynh[B_SZ*SEQL*DINNER];
__device__ __half g_owh[(size_t)DMODEL*DINNER];
__device__ __half g_xs[B_SZ*SEQL*DINNER];
__device__ __half g_B[B_SZ*SEQL*DSTATE];
__device__ __half g_C[B_SZ*SEQL*DSTATE];
__device__ __half g_BT[B_SZ*DSTATE*SEQL];
__device__ __half g_XdT[(size_t)B_SZ*NHEADS*HEADDIM*SEQL];
__device__ __half g_XdecT[(size_t)B_SZ*NHEADS*HEADDIM*SEQL];
__device__ __half g_statesh[(size_t)B_SZ*NCHUNK*NHEADS*HEADDIM*DSTATE];
__device__ __half g_prev[(size_t)B_SZ*NCHUNK*NHEADS*HEADDIM*DSTATE];
__device__ __half g_ygh[B_SZ*SEQL*DINNER];

__device__ __forceinline__ float siluf(float a) { return a / (1.f + expf(-a)); }

// ================= common HMMA helpers =================
__device__ __forceinline__ void mma_fp16(float* c, const uint32_t* a, const uint32_t* b) {
    asm volatile(
        "mma.sync.aligned.m16n8k16.row.col.f32.f16.f16.f32 "
        "{%0,%1,%2,%3}, {%4,%5,%6,%7}, {%8,%9}, {%0,%1,%2,%3};"
        : "+f"(c[0]), "+f"(c[1]), "+f"(c[2]), "+f"(c[3])
        : "r"(a[0]), "r"(a[1]), "r"(a[2]), "r"(a[3]), "r"(b[0]), "r"(b[1]));
}
__device__ __forceinline__ void ldsm4(uint32_t* r, uint32_t addr) {
    asm volatile("ldmatrix.sync.aligned.m8n8.x4.shared.b16 {%0,%1,%2,%3}, [%4];"
        : "=r"(r[0]), "=r"(r[1]), "=r"(r[2]), "=r"(r[3]) : "r"(addr));
}
__device__ __forceinline__ void cp16(uint32_t dst, const void* src) {
    asm volatile("cp.async.cg.shared.global [%0], [%1], 16;" :: "r"(dst), "l"(src));
}
__device__ __forceinline__ uint32_t smem_u32(const void* p) {
    uint32_t a;
    asm("{ .reg .u64 t; cvta.to.shared.u64 t, %1; cvt.u32.u64 %0, t; }" : "=r"(a) : "l"(p));
    return a;
}
__device__ __forceinline__ uint32_t packh2(__half a, __half b) {
    __half2 h = __halves2half2(a, b);
    uint32_t u; memcpy(&u, &h, 4); return u;
}
__device__ __forceinline__ void store2(float* p, float a, float b) {
    *(float2*)p = make_float2(a, b);
}
__device__ __forceinline__ void store2(__half* p, float a, float b) {
    *(__half2*)p = __floats2half2_rn(a, b);
}

// ================= fp16 HMMA GEMM, BK=64, 3 stages, templated output =================
#define OPW64 4096
#define STG64 (2 * OPW64)
#define GEMM1_SMEM (3 * STG64 * 4)        // 98304 B

__device__ __forceinline__ void load_op64(uint32_t sbase_b, const __half* g, int ldk, int tid) {
#pragma unroll
    for (int it = 0; it < 4; it++) {
        int v = tid + (it << 8);
        int r = v >> 3, ch = v & 7;
        int sch = ch ^ (r & 7);
        cp16(sbase_b + (r * 32 + (sch << 2)) * 4, g + (size_t)r * ldk + (ch << 3));
    }
}

template <typename OutT>
__global__ __launch_bounds__(256, 2) void gemm_hmma_out(
    const __half* __restrict__ A, const __half* __restrict__ B,
    OutT* __restrict__ C, int M, int Nreal, int K, float* __restrict__ dtraw)
{
    extern __shared__ uint32_t sw[];
    const uint32_t sb = smem_u32(sw);
    const int tid = threadIdx.x, wid = tid >> 5, lane = tid & 31;
    const int warp_m = wid & 1, warp_n = wid >> 1;
    const int m0 = blockIdx.y << 7, n0 = blockIdx.x << 7;
    const int KT = K >> 6;

    const __half* Ab = A + (size_t)m0 * K;
    const __half* Bb = B + (size_t)n0 * K;

    float acc[4][4][4];
#pragma unroll
    for (int i = 0; i < 4; i++)
#pragma unroll
        for (int j = 0; j < 4; j++)
#pragma unroll
            for (int q = 0; q < 4; q++) acc[i][j][q] = 0.f;

#pragma unroll
    for (int s = 0; s < 2; s++) {
        int koff = s << 6;
        load_op64(sb + (s * STG64) * 4, Ab + koff, K, tid);
        load_op64(sb + (s * STG64 + OPW64) * 4, Bb + koff, K, tid);
        asm volatile("cp.async.commit_group;" ::: "memory");
    }

    const int rowA = warp_m * 64 + ((lane >> 3) & 1) * 8 + (lane & 7);
    const int cA0  = lane >> 4;
    const int rowB = warp_n * 32 + ((lane >> 4) & 1) * 8 + (lane & 7);
    const int cB0  = (lane >> 3) & 1;

    int buf = 0;
    for (int kt = 0; kt < KT; kt++) {
        if (kt + 1 < KT) asm volatile("cp.async.wait_group 1;" ::: "memory");
        else             asm volatile("cp.async.wait_group 0;" ::: "memory");
        __syncthreads();
        if (kt + 2 < KT) {
            int s = buf + 2; if (s >= 3) s -= 3;
            int koff = (kt + 2) << 6;
            load_op64(sb + (s * STG64) * 4, Ab + koff, K, tid);
            load_op64(sb + (s * STG64 + OPW64) * 4, Bb + koff, K, tid);
            asm volatile("cp.async.commit_group;" ::: "memory");
        }

        const uint32_t sA = sb + (uint32_t)buf * STG64 * 4u;
        const uint32_t sB = sA + OPW64 * 4u;

#pragma unroll
        for (int kk = 0; kk < 4; kk++) {
            uint32_t a[4][4];
#pragma unroll
            for (int mi = 0; mi < 4; mi++) {
                int r = rowA + mi * 16;
                uint32_t off = (r * 32 + ((((kk << 1) + cA0) ^ (r & 7)) << 2)) * 4u;
                ldsm4(a[mi], sA + off);
            }
#pragma unroll
            for (int np = 0; np < 2; np++) {
                int r = rowB + np * 16;
                uint32_t boff = (r * 32 + ((((kk << 1) + cB0) ^ (r & 7)) << 2)) * 4u;
                uint32_t b[4];
                ldsm4(b, sB + boff);
#pragma unroll
                for (int mi = 0; mi < 4; mi++) {
                    mma_fp16(acc[mi][2 * np], a[mi], b);
                    mma_fp16(acc[mi][2 * np + 1], a[mi], b + 2);
                }
            }
        }
        buf++; if (buf == 3) buf = 0;
    }

#pragma unroll
    for (int mi = 0; mi < 4; mi++) {
        int rg0 = m0 + warp_m * 64 + mi * 16 + (lane >> 2);
#pragma unroll
        for (int ni = 0; ni < 4; ni++) {
            int cg = n0 + warp_n * 32 + ni * 8 + ((lane & 3) << 1);
            if (cg < Nreal) {
                store2(C + (size_t)rg0 * Nreal + cg, acc[mi][ni][0], acc[mi][ni][1]);
                store2(C + (size_t)(rg0 + 8) * Nreal + cg, acc[mi][ni][2], acc[mi][ni][3]);
                if (dtraw && cg >= DT_COL0) {   // fp32 side copy of dt-raw columns
                    store2(dtraw + (size_t)rg0 * NHEADS + (cg - DT_COL0),
                           acc[mi][ni][0], acc[mi][ni][1]);
                    store2(dtraw + (size_t)(rg0 + 8) * NHEADS + (cg - DT_COL0),
                           acc[mi][ni][2], acc[mi][ni][3]);
                }
            }
        }
    }
}

// ---------------- merged fp32 -> fp16 converts ----------------
#define CVT_N1 ((long)B_SZ*SEQL*DMODEL)
#define CVT_NS2 ((long)D_IN_PROJ*DMODEL)
#define CVT_NT2 ((long)DIP_PAD*DMODEL)
#define CVT_N3 ((long)DMODEL*DINNER)
#define CVT_B1 ((unsigned)(CVT_N1/4/256))
#define CVT_B2 ((unsigned)(CVT_NT2/4/256))
#define CVT_B3 ((unsigned)(CVT_N3/4/256))

__global__ void cvt_all(const float* __restrict__ x, const float* __restrict__ wi,
                        const float* __restrict__ wo,
                        __half* __restrict__ xh, __half* __restrict__ wih,
                        __half* __restrict__ owh)
{
    unsigned bid = blockIdx.x;
    const float* src; __half* dst; long i, n_src;
    if (bid < CVT_B1) {
        i = ((long)bid * 256 + threadIdx.x) * 4; src = x; dst = xh; n_src = CVT_N1;
    } else if (bid < CVT_B1 + CVT_B2) {
        i = ((long)(bid - CVT_B1) * 256 + threadIdx.x) * 4; src = wi; dst = wih; n_src = CVT_NS2;
    } else {
        i = ((long)(bid - CVT_B1 - CVT_B2) * 256 + threadIdx.x) * 4; src = wo; dst = owh; n_src = CVT_N3;
    }
    float4 v = (i < n_src) ? *(const float4*)(src + i) : make_float4(0.f, 0.f, 0.f, 0.f);
    __half2* dp = (__half2*)(dst + i);
    dp[0] = __floats2half2_rn(v.x, v.y);
    dp[1] = __floats2half2_rn(v.z, v.w);
}

// ---------------- merged conv+silu (fp16 in/out) and dt softplus+cumsum (fp32 raw) ----------------
__global__ void conv_dt_kernel(const float* __restrict__ conv_w,
                               const float* __restrict__ conv_b,
                               const float* __restrict__ dt_bias,
                               const float* __restrict__ A_log)
{
    __shared__ float s[CHUNKL];
    if (blockIdx.x < 1024) {
        int idx = blockIdx.x;
        int c = idx % NCHUNK; idx /= NCHUNK;
        int h = idx % NHEADS;
        int b = idx / NHEADS;
        int l = threadIdx.x;
        int t = c * CHUNKL + l;
        float raw = g_dtraw[(size_t)(b * SEQL + t) * NHEADS + h];
        float xv = raw + dt_bias[h];
        float dt = (xv > 20.f) ? xv : log1pf(expf(xv));
        g_dt[(b * SEQL + t) * NHEADS + h] = dt;
        float dA = dt * (-expf(A_log[h]));
        s[l] = dA;
        __syncthreads();
        for (int off = 1; off < CHUNKL; off <<= 1) {
            float v = (l >= off) ? s[l - off] : 0.f;
            __syncthreads();
            s[l] += v;
            __syncthreads();
        }
        g_Acs[((b * NHEADS + h) * NCHUNK + c) * CHUNKL + l] = s[l];
    } else {
        int bid2 = blockIdx.x - 1024;
        int chunk = bid2 % 17; bid2 /= 17;
        int b = bid2 & 1;
        int t0 = (bid2 >> 1) * 256;
        int c = chunk * 256 + threadIdx.x;
        float w0 = conv_w[c * 4 + 0], w1 = conv_w[c * 4 + 1];
        float w2 = conv_w[c * 4 + 2], w3 = conv_w[c * 4 + 3];
        float bias = conv_b[c];
        const __half* src = g_zxh + (size_t)b * SEQL * D_IN_PROJ + DINNER + c;
        __half* dst; int stride;
        if (c < DINNER) {
            dst = g_xs + (size_t)b * SEQL * DINNER + c;           stride = DINNER;
        } else if (c < DINNER + DSTATE) {
            dst = g_B + (size_t)b * SEQL * DSTATE + (c - DINNER); stride = DSTATE;
        } else {
            dst = g_C + (size_t)b * SEQL * DSTATE + (c - DINNER - DSTATE); stride = DSTATE;
        }
        dst += (size_t)t0 * stride;
        float x0 = (t0 >= 3) ? __half2float(src[(size_t)(t0 - 3) * D_IN_PROJ]) : 0.f;
        float x1 = (t0 >= 2) ? __half2float(src[(size_t)(t0 - 2) * D_IN_PROJ]) : 0.f;
        float x2 = (t0 >= 1) ? __half2float(src[(size_t)(t0 - 1) * D_IN_PROJ]) : 0.f;
        for (int t = 0; t < 256; t++) {
            float x3 = __half2float(src[(size_t)(t0 + t) * D_IN_PROJ]);
            float a = bias + w0 * x0 + w1 * x1 + w2 * x2 + w3 * x3;
            dst[(size_t)t * stride] = __float2half_rn(siluf(a));
            x0 = x1; x1 = x2; x2 = x3;
        }
    }
}

// ---------------- merged SSM operand transposes ----------------
__global__ void cvt_ssm_kernel()
{
    __shared__ float xs[64][65];
    __shared__ float dts[64], dec[64];
    __shared__ __half btile[32][34];
    int tid = threadIdx.x;
    if (blockIdx.x < 512) {
        int i = blockIdx.x;
        int t0 = (i & 63) * 32; i >>= 6;
        int n0 = (i & 3) * 32;
        int b = i >> 2;
#pragma unroll
        for (int it = 0; it < 4; it++) {
            int v = tid + it * 256;
            int t = v >> 5, n = v & 31;
            btile[t][n] = g_B[(size_t)(b * SEQL + t0 + t) * DSTATE + n0 + n];
        }
        __syncthreads();
#pragma unroll
        for (int it = 0; it < 2; it++) {
            int v = tid + it * 256;
            int n = v >> 4, tc = (v & 15) << 1;
            size_t o = (size_t)(b * DSTATE + n0 + n) * SEQL + t0 + tc;
            *(__half2*)(g_BT + o) = __halves2half2(btile[tc][n], btile[tc + 1][n]);
        }
    } else {
        int j = blockIdx.x - 512;
        int tt = j & 31; j >>= 5;
        int h = j & 63;
        int b = j >> 6;
        int t0 = tt * 64;
        int c = t0 >> 8;
        const float* acs = g_Acs + ((b * NHEADS + h) * NCHUNK + c) * CHUNKL;
        if (tid < 64) {
            int tl = (t0 & 255) + tid;
            dts[tid] = g_dt[(size_t)(b * SEQL + t0 + tid) * NHEADS + h];
            dec[tid] = __expf(acs[CHUNKL - 1] - acs[tl]);
        }
#pragma unroll
        for (int it = 0; it < 16; it++) {
            int v = tid + it * 256;
            int t = v >> 6, p = v & 63;
            xs[t][p] = __half2float(g_xs[(size_t)(b * SEQL + t0 + t) * DINNER + h * HEADDIM + p]);
        }
        __syncthreads();
#pragma unroll
        for (int it = 0; it < 8; it++) {
            int v = tid + it * 256;
            int p = v >> 5, tc = (v & 31) << 1;
            size_t o = ((size_t)((b * NHEADS + h) * HEADDIM) + p) * SEQL + t0 + tc;
            float x0 = xs[tc][p] * dts[tc];
            float x1 = xs[tc + 1][p] * dts[tc + 1];
            *(__half2*)(g_XdT + o)   = __floats2half2_rn(x0, x1);
            *(__half2*)(g_XdecT + o) = __floats2half2_rn(x0 * dec[tc], x1 * dec[tc + 1]);
        }
    }
}

// ---------------- states (single fp16 HMMA) -> fp16 output ----------------
#define S_A_O 0
#define S_B_O 2048
#define S_STG 6144
#define S_SMEM_BYTES (2 * S_STG * 4)

__global__ __launch_bounds__(256, 2) void states_hmma()
{
    extern __shared__ uint32_t sw[];
    const uint32_t sb = smem_u32(sw);
    int bid = blockIdx.x;
    int h = bid & 63, cc = (bid >> 6) & 7, b = bid >> 9;
    int tid = threadIdx.x, wid = tid >> 5, lane = tid & 31;
    int warp_m = wid >> 2, warp_n = wid & 3;
    const __half* A = g_XdecT + (size_t)((b * NHEADS + h) * HEADDIM) * SEQL + cc * CHUNKL;
    const __half* B = g_BT + (size_t)(b * DSTATE) * SEQL + cc * CHUNKL;

    float acc[2][4][4];
#pragma unroll
    for (int i = 0; i < 2; i++)
#pragma unroll
        for (int j = 0; j < 4; j++)
#pragma unroll
            for (int q = 0; q < 4; q++) acc[i][j][q] = 0.f;

    auto load_stage = [&](int kc, int buf) {
        uint32_t base = (uint32_t)buf * S_STG;
        int koff = kc * 64;
#pragma unroll
        for (int it = 0; it < 2; it++) {
            int v = tid + (it << 8);
            int r = v >> 3, ch = v & 7;
            int sch = ch ^ (r & 7);
            cp16(sb + (base + S_A_O + r * 32 + sch * 4) * 4, A + (size_t)r * SEQL + koff + ch * 8);
        }
#pragma unroll
        for (int it = 0; it < 4; it++) {
            int v = tid + (it << 8);
            int r = v >> 3, ch = v & 7;
            int sch = ch ^ (r & 7);
            cp16(sb + (base + S_B_O + r * 32 + sch * 4) * 4, B + (size_t)r * SEQL + koff + ch * 8);
        }
        asm volatile("cp.async.commit_group;" ::: "memory");
    };

    load_stage(0, 0);
    load_stage(1, 1);

    const int arow = warp_m * 32 + ((lane >> 3) & 1) * 8 + (lane & 7);
    const int cA0 = lane >> 4;
    const int brl = ((lane >> 4) & 1) * 8 + (lane & 7);
    const int cB0 = (lane >> 3) & 1;

    for (int kc = 0; kc < 4; kc++) {
        if (kc < 3) asm volatile("cp.async.wait_group 1;" ::: "memory");
        else        asm volatile("cp.async.wait_group 0;" ::: "memory");
        __syncthreads();
        uint32_t base = (uint32_t)(kc & 1) * S_STG;
#pragma unroll
        for (int kk = 0; kk < 4; kk++) {
            uint32_t a[2][4];
#pragma unroll
            for (int mi = 0; mi < 2; mi++) {
                int r = arow + mi * 16;
                uint32_t w = base + S_A_O + r * 32 + ((((kk << 1) + cA0) ^ (r & 7)) << 2);
                ldsm4(a[mi], sb + w * 4);
            }
#pragma unroll
            for (int np = 0; np < 2; np++) {
                int rb = warp_n * 32 + np * 16 + brl;
                uint32_t w = base + S_B_O + rb * 32 + ((((kk << 1) + cB0) ^ (rb & 7)) << 2);
                uint32_t bf[4];
                ldsm4(bf, sb + w * 4);
#pragma unroll
                for (int mi = 0; mi < 2; mi++) {
                    mma_fp16(acc[mi][2 * np], a[mi], bf);
                    mma_fp16(acc[mi][2 * np + 1], a[mi], bf + 2);
                }
            }
        }
        __syncthreads();
        if (kc + 2 < 4) load_stage(kc + 2, kc & 1);
    }

    __half* out = g_statesh + (size_t)((b * NCHUNK + cc) * NHEADS + h) * HEADDIM * DSTATE;
#pragma unroll
    for (int mi = 0; mi < 2; mi++) {
        int r0 = warp_m * 32 + mi * 16 + (lane >> 2);
#pragma unroll
        for (int ni = 0; ni < 4; ni++) {
            int col = warp_n * 32 + ni * 8 + 2 * (lane & 3);
            *(__half2*)(out + (size_t)r0 * DSTATE + col) =
                __floats2half2_rn(acc[mi][ni][0], acc[mi][ni][1]);
            *(__half2*)(out + (size_t)(r0 + 8) * DSTATE + col) =
                __floats2half2_rn(acc[mi][ni][2], acc[mi][ni][3]);
        }
    }
}

// ---------------- inter-chunk recurrence ----------------
__global__ __launch_bounds__(1024) void prev_kernel()
{
    int b = blockIdx.x >> 6;
    int h = blockIdx.x & 63;
    int tid = threadIdx.x;
    float P[8];
#pragma unroll
    for (int i = 0; i < 8; i++) P[i] = 0.f;
    for (int c = 0; c < NCHUNK; c++) {
        float decay = __expf(g_Acs[((b * NHEADS + h) * NCHUNK + c) * CHUNKL + CHUNKL - 1]);
        size_t base = (size_t)((b * NCHUNK + c) * NHEADS + h) * HEADDIM * DSTATE;
#pragma unroll
        for (int i = 0; i < 8; i++) {
            int e = i * 1024 + tid;
            float v = P[i];
            g_prev[base + e] = __float2half_rn(v);
            P[i] = v * decay + __half2float(g_statesh[base + e]);
        }
    }
}

// ---------------- Y via single fp16 HMMA -> fp16 out + fused sumsq ----------------
#define Y_ACS_O 0
#define Y_C_O 256
#define Y_PV_O (Y_C_O + 4352)
#define Y_B0_O (Y_PV_O + 4352)
#define Y_B1_O (Y_B0_O + 4352)
#define Y_X0_O (Y_B1_O + 4352)
#define Y_X1_O (Y_X0_O + 2304)
#define Y_S_O  (Y_X1_O + 2304)
#define Y_SMEM_BYTES ((Y_S_O + 2304) * 4)

__global__ __launch_bounds__(256, 2) void y_hmma(const float* __restrict__ Dp)
{
    extern __shared__ uint32_t sw[];
    const uint32_t sb = smem_u32(sw);
    float* acs_s = (float*)(sw + Y_ACS_O);
    int bid = blockIdx.x;
    int lt = bid & 3, h = (bid >> 2) & 63, c = (bid >> 8) & 7, b = bid >> 11;
    int tid = threadIdx.x, wid = tid >> 5, lane = tid & 31;
    int warp_m = wid >> 2, warp_n = wid & 3;
    int l0 = lt * 64;
    const int bt0 = b * SEQL + c * CHUNKL;

    acs_s[tid] = g_Acs[((b * NHEADS + h) * NCHUNK + c) * CHUNKL + tid];

    const __half* gB = g_B + (size_t)bt0 * DSTATE;
    const __half* gX = g_XdT + (size_t)((b * NHEADS + h) * HEADDIM) * SEQL + c * CHUNKL;

    auto load_bx = [&](int st, int pbuf) {
        const __half* Bp = gB + (size_t)(st * 64) * DSTATE;
        const __half* Xp = gX + st * 64;
        uint32_t bo = pbuf ? (uint32_t)Y_B1_O : (uint32_t)Y_B0_O;
        uint32_t xo = pbuf ? (uint32_t)Y_X1_O : (uint32_t)Y_X0_O;
#pragma unroll
        for (int it = 0; it < 4; it++) {
            int v = tid + (it << 8);
            int r = v >> 4, ch = v & 15;
            cp16(sb + (bo + r * 68 + ch * 4) * 4, Bp + (size_t)r * DSTATE + ch * 8);
        }
#pragma unroll
        for (int it = 0; it < 2; it++) {
            int v = tid + (it << 8);
            int r = v >> 3, ch = v & 7;
            cp16(sb + (xo + r * 36 + ch * 4) * 4, Xp + (size_t)r * SEQL + ch * 8);
        }
        asm volatile("cp.async.commit_group;" ::: "memory");
    };

    {
        const __half* sC = g_C + (size_t)(bt0 + l0) * DSTATE;
        size_t pb = (size_t)((b * NCHUNK + c) * NHEADS + h) * HEADDIM * DSTATE;
        const __half* sP = g_prev + pb;
#pragma unroll
        for (int it = 0; it < 4; it++) {
            int v = tid + (it << 8);
            int r = v >> 4, ch = v & 15;
            cp16(sb + (Y_C_O + r * 68 + ch * 4) * 4, sC + (size_t)r * DSTATE + ch * 8);
            cp16(sb + (Y_PV_O + r * 68 + ch * 4) * 4, sP + (size_t)r * DSTATE + ch * 8);
        }
        asm volatile("cp.async.commit_group;" ::: "memory");
    }
    load_bx(0, 0);

    asm volatile("cp.async.wait_group 1;" ::: "memory");
    __syncthreads();

    float Yacc[2][2][4];
#pragma unroll
    for (int i = 0; i < 2; i++)
#pragma unroll
        for (int j = 0; j < 2; j++)
#pragma unroll
            for (int q = 0; q < 4; q++) Yacc[i][j][q] = 0.f;

    const int arow = warp_m * 32 + ((lane >> 3) & 1) * 8 + (lane & 7);
    const int akw  = (lane >> 4) << 2;
    const int brow = warp_n * 16 + ((lane >> 4) & 1) * 8 + (lane & 7);
    const int bkw  = ((lane >> 3) & 1) << 2;

#pragma unroll
    for (int kk = 0; kk < 8; kk++) {
        uint32_t a[2][4], bf[4];
#pragma unroll
        for (int mi = 0; mi < 2; mi++)
            ldsm4(a[mi], sb + (uint32_t)(Y_C_O + (arow + mi * 16) * 68 + kk * 8 + akw) * 4);
        ldsm4(bf, sb + (uint32_t)(Y_PV_O + brow * 68 + kk * 8 + bkw) * 4);
#pragma unroll
        for (int mi = 0; mi < 2; mi++) {
            mma_fp16(Yacc[mi][0], a[mi], bf);
            mma_fp16(Yacc[mi][1], a[mi], bf + 2);
        }
    }
#pragma unroll
    for (int mi = 0; mi < 2; mi++) {
        int r0 = l0 + warp_m * 32 + mi * 16 + (lane >> 2);
        float e0 = __expf(acs_s[r0]);
        float e1 = __expf(acs_s[r0 + 8]);
#pragma unroll
        for (int ni = 0; ni < 2; ni++) {
            Yacc[mi][ni][0] *= e0; Yacc[mi][ni][1] *= e0;
            Yacc[mi][ni][2] *= e1; Yacc[mi][ni][3] *= e1;
        }
    }

    for (int st = 0; st <= lt; st++) {
        if (st + 1 <= lt) {
            load_bx(st + 1, (st + 1) & 1);
            asm volatile("cp.async.wait_group 1;" ::: "memory");
        } else {
            asm volatile("cp.async.wait_group 0;" ::: "memory");
        }
        __syncthreads();

        const uint32_t bo = (st & 1) ? (uint32_t)Y_B1_O : (uint32_t)Y_B0_O;
        const uint32_t xo = (st & 1) ? (uint32_t)Y_X1_O : (uint32_t)Y_X0_O;
        int s0 = st * 64;

        float sacc[2][2][4];
#pragma unroll
        for (int i = 0; i < 2; i++)
#pragma unroll
            for (int j = 0; j < 2; j++)
#pragma unroll
                for (int q = 0; q < 4; q++) sacc[i][j][q] = 0.f;
#pragma unroll
        for (int kk = 0; kk < 8; kk++) {
            uint32_t a[2][4], bf[4];
#pragma unroll
            for (int mi = 0; mi < 2; mi++)
                ldsm4(a[mi], sb + (uint32_t)(Y_C_O + (arow + mi * 16) * 68 + kk * 8 + akw) * 4);
            ldsm4(bf, sb + (bo + brow * 68 + kk * 8 + bkw) * 4);
#pragma unroll
            for (int mi = 0; mi < 2; mi++) {
                mma_fp16(sacc[mi][0], a[mi], bf);
                mma_fp16(sacc[mi][1], a[mi], bf + 2);
            }
        }
#pragma unroll
        for (int mi = 0; mi < 2; mi++) {
            int rr0 = warp_m * 32 + mi * 16 + (lane >> 2);
            int lg0 = l0 + rr0, lg1 = lg0 + 8;
            float a0 = acs_s[lg0], a1 = acs_s[lg1];
#pragma unroll
            for (int ni = 0; ni < 2; ni++) {
                int ccc = warp_n * 16 + ni * 8 + 2 * (lane & 3);
                int sg = s0 + ccc;
                float as0 = acs_s[sg], as1 = acs_s[sg + 1];
                float v00 = (sg     <= lg0) ? sacc[mi][ni][0] * __expf(a0 - as0) : 0.f;
                float v01 = (sg + 1 <= lg0) ? sacc[mi][ni][1] * __expf(a0 - as1) : 0.f;
                float v10 = (sg     <= lg1) ? sacc[mi][ni][2] * __expf(a1 - as0) : 0.f;
                float v11 = (sg + 1 <= lg1) ? sacc[mi][ni][3] * __expf(a1 - as1) : 0.f;
                sw[Y_S_O + rr0 * 36 + (ccc >> 1)] =
                    packh2(__float2half_rn(v00), __float2half_rn(v01));
                sw[Y_S_O + (rr0 + 8) * 36 + (ccc >> 1)] =
                    packh2(__float2half_rn(v10), __float2half_rn(v11));
            }
        }
        __syncthreads();
#pragma unroll
        for (int kk = 0; kk < 4; kk++) {
            uint32_t a[2][4], bf[4];
#pragma unroll
            for (int mi = 0; mi < 2; mi++)
                ldsm4(a[mi], sb + (uint32_t)(Y_S_O + (arow + mi * 16) * 36 + kk * 8 + akw) * 4);
            ldsm4(bf, sb + (xo + brow * 36 + kk * 8 + bkw) * 4);
#pragma unroll
            for (int mi = 0; mi < 2; mi++) {
                mma_fp16(Yacc[mi][0], a[mi], bf);
                mma_fp16(Yacc[mi][1], a[mi], bf + 2);
            }
        }
    }

    // epilogue: + D*x_ssm, gate silu(z fp16), fp16 store + row sumsq atomics
    float Dh = Dp[h];
#pragma unroll
    for (int mi = 0; mi < 2; mi++) {
#pragma unroll
        for (int q = 0; q < 2; q++) {
            int rr = warp_m * 32 + mi * 16 + (lane >> 2) + q * 8;
            int t = bt0 + l0 + rr;
            float local = 0.f;
#pragma unroll
            for (int ni = 0; ni < 2; ni++) {
                int pp = warp_n * 16 + ni * 8 + 2 * (lane & 3);
                float2 xs = __half22float2(*(const __half2*)(g_xs + (size_t)t * DINNER + h * HEADDIM + pp));
                float2 zz = __half22float2(*(const __half2*)(g_zxh + (size_t)t * D_IN_PROJ + h * HEADDIM + pp));
                float y0 = (Yacc[mi][ni][q * 2 + 0] + xs.x * Dh) * siluf(zz.x);
                float y1 = (Yacc[mi][ni][q * 2 + 1] + xs.y * Dh) * siluf(zz.y);
                *(__half2*)(g_ygh + (size_t)t * DINNER + h * HEADDIM + pp) = __floats2half2_rn(y0, y1);
                local += y0 * y0 + y1 * y1;
            }
            local += __shfl_xor_sync(0xFFFFFFFFu, local, 1);
            local += __shfl_xor_sync(0xFFFFFFFFu, local, 2);
            if ((lane & 3) == 0) atomicAdd(&g_ss[t], local);
        }
    }
}

// ---------------- RMSNorm scale pass -> fp16 ----------------
__global__ __launch_bounds__(256) void rmsnorm_kernel(const float* __restrict__ w)
{
    int row = blockIdx.x;
    const __half* y = g_ygh + (size_t)row * DINNER;
    __half* oh = g_ynh + (size_t)row * DINNER;
    int tid = threadIdx.x;
    float scale = rsqrtf(g_ss[row] / (float)DINNER + EPSV);
#pragma unroll
    for (int it = 0; it < 4; it++) {
        int i = it * 1024 + tid * 4;
        float2 v0 = __half22float2(*(const __half2*)(y + i));
        float2 v1 = __half22float2(*(const __half2*)(y + i + 2));
        float4 wv = *(const float4*)(w + i);
        __half2* hp = (__half2*)(oh + i);
        hp[0] = __floats2half2_rn(v0.x * scale * wv.x, v0.y * scale * wv.y);
        hp[1] = __floats2half2_rn(v1.x * scale * wv.z, v1.y * scale * wv.w);
    }
}

// ---------------- launch ----------------
extern "C" void kernel_launch(void* const* d_in, const int* in_sizes, int n_in,
                              void* d_out, int out_size)
{
    const float* x          = (const float*)d_in[0];
    const float* in_proj_w  = (const float*)d_in[1];
    const float* conv_w     = (const float*)d_in[2];
    const float* conv_b     = (const float*)d_in[3];
    const float* dt_bias    = (const float*)d_in[4];
    const float* A_log      = (const float*)d_in[5];
    const float* Dp         = (const float*)d_in[6];
    const float* norm_w     = (const float*)d_in[7];
    const float* out_proj_w = (const float*)d_in[8];
    float* out = (float*)d_out;

    float *ss_p = nullptr, *dtraw_p = nullptr;
    __half *zxh_p, *xh_p, *wih_p, *ynh_p, *owh_p;
    cudaGetSymbolAddress((void**)&ss_p, g_ss);
    cudaGetSymbolAddress((void**)&dtraw_p, g_dtraw);
    cudaGetSymbolAddress((void**)&zxh_p, g_zxh);
    cudaGetSymbolAddress((void**)&xh_p, g_xh);
    cudaGetSymbolAddress((void**)&wih_p, g_wih);
    cudaGetSymbolAddress((void**)&ynh_p, g_ynh);
    cudaGetSymbolAddress((void**)&owh_p, g_owh);

    static bool attr_set = false;
    if (!attr_set) {
        cudaFuncSetAttribute(gemm_hmma_out<__half>, cudaFuncAttributeMaxDynamicSharedMemorySize, GEMM1_SMEM);
        cudaFuncSetAttribute(gemm_hmma_out<float>, cudaFuncAttributeMaxDynamicSharedMemorySize, GEMM1_SMEM);
        cudaFuncSetAttribute(states_hmma, cudaFuncAttributeMaxDynamicSharedMemorySize, S_SMEM_BYTES);
        cudaFuncSetAttribute(y_hmma, cudaFuncAttributeMaxDynamicSharedMemorySize, Y_SMEM_BYTES);
        attr_set = true;
    }

    const int M = B_SZ * SEQL; // 4096

    // 0) merged converts
    cvt_all<<<CVT_B1 + CVT_B2 + CVT_B3, 256>>>(x, in_proj_w, out_proj_w, xh_p, wih_p, owh_p);

    // 1) in_proj GEMM -> fp16 zx + fp32 dt-raw side copy
    gemm_hmma_out<__half><<<dim3(DIP_PAD / 128, M / 128), 256, GEMM1_SMEM>>>(
        xh_p, wih_p, zxh_p, M, D_IN_PROJ, DMODEL, dtraw_p);

    // zero sumsq for y_hmma accumulation
    cudaMemsetAsync(ss_p, 0, B_SZ * SEQL * sizeof(float));

    // 2+3) conv+silu and dt softplus+cumsum, merged
    conv_dt_kernel<<<1024 + 17 * B_SZ * (SEQL / 256), 256>>>(conv_w, conv_b, dt_bias, A_log);

    // 4) SSM operand transposes, merged
    cvt_ssm_kernel<<<512 + (SEQL / 64) * NHEADS * B_SZ, 256>>>();

    // 5) states
    states_hmma<<<B_SZ * NCHUNK * NHEADS, 256, S_SMEM_BYTES>>>();

    // 6) recurrence
    prev_kernel<<<B_SZ * NHEADS, 1024>>>();

    // 7) Y + gate + sumsq
    y_hmma<<<B_SZ * NCHUNK * NHEADS * 4, 256, Y_SMEM_BYTES>>>(Dp);

    // 8) RMSNorm scale
    rmsnorm_kernel<<<B_SZ * SEQL, 256>>>(norm_w);

    // 9) out_proj GEMM -> fp32 output
    gemm_hmma_out<float><<<dim3(DMODEL / 128, M / 128), 256, GEMM1_SMEM>>>(
        ynh_p, owh_p, out, M, DMODEL, DINNER, nullptr);

    (void)in_sizes; (void)n_in; (void)out_size;
}

// round 15
// speedup vs baseline: 1.0632x; 1.0092x over previous
#include <cuda_runtime.h>
#include <cuda_bf16.h>
#include <cuda_fp16.h>
#include <cstdint>
#include <cstring>

#define B_SZ 2
#define SEQL 2048
#define DMODEL 2048
#define DINNER 4096
#define DSTATE 128
#define HEADDIM 64
#define NHEADS 64
#define CHUNKL 256
#define NCHUNK 8
#define CONV_DIM 4352     // DINNER + 2*DSTATE
#define D_IN_PROJ 8512    // 2*DINNER + 2*DSTATE + NHEADS
#define DIP_PAD 8576      // 67*128
#define DT_COL0 (DINNER + CONV_DIM)      // 8448
#define EPSV 1e-5f

// ---------------- scratch ----------------
__device__ float g_dtraw[B_SZ*SEQL*NHEADS];
__device__ float g_dt[B_SZ*SEQL*NHEADS];
__device__ float g_Acs[B_SZ*NHEADS*NCHUNK*CHUNKL];
__device__ float g_ss[B_SZ*SEQL];
// fp16 gemm operands / activations
__device__ __half g_zxh[(size_t)B_SZ*SEQL*D_IN_PROJ];
__device__ __half g_xh[B_SZ*SEQL*DMODEL];
__device__ __half g_wih[(size_t)DIP_PAD*DMODEL];
__device__ __half g_owh[(size_t)DMODEL*DINNER];   // out_proj_w * norm_w (pre-fused)
__device__ __half g_xs[B_SZ*SEQL*DINNER];
__device__ __half g_B[B_SZ*SEQL*DSTATE];
__device__ __half g_C[B_SZ*SEQL*DSTATE];
__device__ __half g_BT[B_SZ*DSTATE*SEQL];
__device__ __half g_XdT[(size_t)B_SZ*NHEADS*HEADDIM*SEQL];
__device__ __half g_XdecT[(size_t)B_SZ*NHEADS*HEADDIM*SEQL];
__device__ __half g_statesh[(size_t)B_SZ*NCHUNK*NHEADS*HEADDIM*DSTATE];
__device__ __half g_prev[(size_t)B_SZ*NCHUNK*NHEADS*HEADDIM*DSTATE];
__device__ __half g_ygh[B_SZ*SEQL*DINNER];

__device__ __forceinline__ float siluf(float a) { return a / (1.f + expf(-a)); }

// ================= common HMMA helpers =================
__device__ __forceinline__ void mma_fp16(float* c, const uint32_t* a, const uint32_t* b) {
    asm volatile(
        "mma.sync.aligned.m16n8k16.row.col.f32.f16.f16.f32 "
        "{%0,%1,%2,%3}, {%4,%5,%6,%7}, {%8,%9}, {%0,%1,%2,%3};"
        : "+f"(c[0]), "+f"(c[1]), "+f"(c[2]), "+f"(c[3])
        : "r"(a[0]), "r"(a[1]), "r"(a[2]), "r"(a[3]), "r"(b[0]), "r"(b[1]));
}
__device__ __forceinline__ void ldsm4(uint32_t* r, uint32_t addr) {
    asm volatile("ldmatrix.sync.aligned.m8n8.x4.shared.b16 {%0,%1,%2,%3}, [%4];"
        : "=r"(r[0]), "=r"(r[1]), "=r"(r[2]), "=r"(r[3]) : "r"(addr));
}
__device__ __forceinline__ void cp16(uint32_t dst, const void* src) {
    asm volatile("cp.async.cg.shared.global [%0], [%1], 16;" :: "r"(dst), "l"(src));
}
__device__ __forceinline__ uint32_t smem_u32(const void* p) {
    uint32_t a;
    asm("{ .reg .u64 t; cvta.to.shared.u64 t, %1; cvt.u32.u64 %0, t; }" : "=r"(a) : "l"(p));
    return a;
}
__device__ __forceinline__ uint32_t packh2(__half a, __half b) {
    __half2 h = __halves2half2(a, b);
    uint32_t u; memcpy(&u, &h, 4); return u;
}
__device__ __forceinline__ void store2(float* p, float a, float b) {
    *(float2*)p = make_float2(a, b);
}
__device__ __forceinline__ void store2(__half* p, float a, float b) {
    *(__half2*)p = __floats2half2_rn(a, b);
}

// ================= fp16 HMMA GEMM, BK=64, 3 stages, templated output =================
#define OPW64 4096
#define STG64 (2 * OPW64)
#define GEMM1_SMEM (3 * STG64 * 4)        // 98304 B

__device__ __forceinline__ void load_op64(uint32_t sbase_b, const __half* g, int ldk, int tid) {
#pragma unroll
    for (int it = 0; it < 4; it++) {
        int v = tid + (it << 8);
        int r = v >> 3, ch = v & 7;
        int sch = ch ^ (r & 7);
        cp16(sbase_b + (r * 32 + (sch << 2)) * 4, g + (size_t)r * ldk + (ch << 3));
    }
}

// dtraw: optional fp32 side copy of columns >= DT_COL0 (in_proj only)
// rowss: optional per-row sum-of-squares -> rsqrt scale applied in epilogue (out_proj only)
template <typename OutT>
__global__ __launch_bounds__(256, 2) void gemm_hmma_out(
    const __half* __restrict__ A, const __half* __restrict__ B,
    OutT* __restrict__ C, int M, int Nreal, int K,
    float* __restrict__ dtraw, const float* __restrict__ rowss)
{
    extern __shared__ uint32_t sw[];
    const uint32_t sb = smem_u32(sw);
    const int tid = threadIdx.x, wid = tid >> 5, lane = tid & 31;
    const int warp_m = wid & 1, warp_n = wid >> 1;
    const int m0 = blockIdx.y << 7, n0 = blockIdx.x << 7;
    const int KT = K >> 6;

    const __half* Ab = A + (size_t)m0 * K;
    const __half* Bb = B + (size_t)n0 * K;

    float acc[4][4][4];
#pragma unroll
    for (int i = 0; i < 4; i++)
#pragma unroll
        for (int j = 0; j < 4; j++)
#pragma unroll
            for (int q = 0; q < 4; q++) acc[i][j][q] = 0.f;

#pragma unroll
    for (int s = 0; s < 2; s++) {
        int koff = s << 6;
        load_op64(sb + (s * STG64) * 4, Ab + koff, K, tid);
        load_op64(sb + (s * STG64 + OPW64) * 4, Bb + koff, K, tid);
        asm volatile("cp.async.commit_group;" ::: "memory");
    }

    const int rowA = warp_m * 64 + ((lane >> 3) & 1) * 8 + (lane & 7);
    const int cA0  = lane >> 4;
    const int rowB = warp_n * 32 + ((lane >> 4) & 1) * 8 + (lane & 7);
    const int cB0  = (lane >> 3) & 1;

    int buf = 0;
    for (int kt = 0; kt < KT; kt++) {
        if (kt + 1 < KT) asm volatile("cp.async.wait_group 1;" ::: "memory");
        else             asm volatile("cp.async.wait_group 0;" ::: "memory");
        __syncthreads();
        if (kt + 2 < KT) {
            int s = buf + 2; if (s >= 3) s -= 3;
            int koff = (kt + 2) << 6;
            load_op64(sb + (s * STG64) * 4, Ab + koff, K, tid);
            load_op64(sb + (s * STG64 + OPW64) * 4, Bb + koff, K, tid);
            asm volatile("cp.async.commit_group;" ::: "memory");
        }

        const uint32_t sA = sb + (uint32_t)buf * STG64 * 4u;
        const uint32_t sB = sA + OPW64 * 4u;

#pragma unroll
        for (int kk = 0; kk < 4; kk++) {
            uint32_t a[4][4];
#pragma unroll
            for (int mi = 0; mi < 4; mi++) {
                int r = rowA + mi * 16;
                uint32_t off = (r * 32 + ((((kk << 1) + cA0) ^ (r & 7)) << 2)) * 4u;
                ldsm4(a[mi], sA + off);
            }
#pragma unroll
            for (int np = 0; np < 2; np++) {
                int r = rowB + np * 16;
                uint32_t boff = (r * 32 + ((((kk << 1) + cB0) ^ (r & 7)) << 2)) * 4u;
                uint32_t b[4];
                ldsm4(b, sB + boff);
#pragma unroll
                for (int mi = 0; mi < 4; mi++) {
                    mma_fp16(acc[mi][2 * np], a[mi], b);
                    mma_fp16(acc[mi][2 * np + 1], a[mi], b + 2);
                }
            }
        }
        buf++; if (buf == 3) buf = 0;
    }

#pragma unroll
    for (int mi = 0; mi < 4; mi++) {
        int rg0 = m0 + warp_m * 64 + mi * 16 + (lane >> 2);
        float sc0 = 1.f, sc1 = 1.f;
        if (rowss) {
            sc0 = rsqrtf(rowss[rg0] / (float)DINNER + EPSV);
            sc1 = rsqrtf(rowss[rg0 + 8] / (float)DINNER + EPSV);
        }
#pragma unroll
        for (int ni = 0; ni < 4; ni++) {
            int cg = n0 + warp_n * 32 + ni * 8 + ((lane & 3) << 1);
            if (cg < Nreal) {
                store2(C + (size_t)rg0 * Nreal + cg, acc[mi][ni][0] * sc0, acc[mi][ni][1] * sc0);
                store2(C + (size_t)(rg0 + 8) * Nreal + cg, acc[mi][ni][2] * sc1, acc[mi][ni][3] * sc1);
                if (dtraw && cg >= DT_COL0) {
                    store2(dtraw + (size_t)rg0 * NHEADS + (cg - DT_COL0),
                           acc[mi][ni][0], acc[mi][ni][1]);
                    store2(dtraw + (size_t)(rg0 + 8) * NHEADS + (cg - DT_COL0),
                           acc[mi][ni][2], acc[mi][ni][3]);
                }
            }
        }
    }
}

// ---------------- merged fp32 -> fp16 converts (out_proj_w fused with norm_w) ----------------
#define CVT_N1 ((long)B_SZ*SEQL*DMODEL)
#define CVT_NS2 ((long)D_IN_PROJ*DMODEL)
#define CVT_NT2 ((long)DIP_PAD*DMODEL)
#define CVT_N3 ((long)DMODEL*DINNER)
#define CVT_B1 ((unsigned)(CVT_N1/4/256))
#define CVT_B2 ((unsigned)(CVT_NT2/4/256))
#define CVT_B3 ((unsigned)(CVT_N3/4/256))

__global__ void cvt_all(const float* __restrict__ x, const float* __restrict__ wi,
                        const float* __restrict__ wo, const float* __restrict__ norm_w,
                        __half* __restrict__ xh, __half* __restrict__ wih,
                        __half* __restrict__ owh)
{
    unsigned bid = blockIdx.x;
    if (bid < CVT_B1) {
        long i = ((long)bid * 256 + threadIdx.x) * 4;
        float4 v = *(const float4*)(x + i);
        __half2* dp = (__half2*)(xh + i);
        dp[0] = __floats2half2_rn(v.x, v.y);
        dp[1] = __floats2half2_rn(v.z, v.w);
    } else if (bid < CVT_B1 + CVT_B2) {
        long i = ((long)(bid - CVT_B1) * 256 + threadIdx.x) * 4;
        float4 v = (i < CVT_NS2) ? *(const float4*)(wi + i) : make_float4(0.f, 0.f, 0.f, 0.f);
        __half2* dp = (__half2*)(wih + i);
        dp[0] = __floats2half2_rn(v.x, v.y);
        dp[1] = __floats2half2_rn(v.z, v.w);
    } else {
        long i = ((long)(bid - CVT_B1 - CVT_B2) * 256 + threadIdx.x) * 4;
        float4 v = *(const float4*)(wo + i);
        int e = (int)(i & (DINNER - 1));
        float4 wv = *(const float4*)(norm_w + e);
        __half2* dp = (__half2*)(owh + i);
        dp[0] = __floats2half2_rn(v.x * wv.x, v.y * wv.y);
        dp[1] = __floats2half2_rn(v.z * wv.z, v.w * wv.w);
    }
}

// ---------------- merged conv+silu (fp16 in/out) and dt softplus+cumsum (fp32 raw) ----------------
__global__ void conv_dt_kernel(const float* __restrict__ conv_w,
                               const float* __restrict__ conv_b,
                               const float* __restrict__ dt_bias,
                               const float* __restrict__ A_log)
{
    __shared__ float s[CHUNKL];
    if (blockIdx.x < 1024) {
        int idx = blockIdx.x;
        int c = idx % NCHUNK; idx /= NCHUNK;
        int h = idx % NHEADS;
        int b = idx / NHEADS;
        int l = threadIdx.x;
        int t = c * CHUNKL + l;
        float raw = g_dtraw[(size_t)(b * SEQL + t) * NHEADS + h];
        float xv = raw + dt_bias[h];
        float dt = (xv > 20.f) ? xv : log1pf(expf(xv));
        g_dt[(b * SEQL + t) * NHEADS + h] = dt;
        float dA = dt * (-expf(A_log[h]));
        s[l] = dA;
        __syncthreads();
        for (int off = 1; off < CHUNKL; off <<= 1) {
            float v = (l >= off) ? s[l - off] : 0.f;
            __syncthreads();
            s[l] += v;
            __syncthreads();
        }
        g_Acs[((b * NHEADS + h) * NCHUNK + c) * CHUNKL + l] = s[l];
    } else {
        int bid2 = blockIdx.x - 1024;
        int chunk = bid2 % 17; bid2 /= 17;
        int b = bid2 & 1;
        int t0 = (bid2 >> 1) * 256;
        int c = chunk * 256 + threadIdx.x;
        float w0 = conv_w[c * 4 + 0], w1 = conv_w[c * 4 + 1];
        float w2 = conv_w[c * 4 + 2], w3 = conv_w[c * 4 + 3];
        float bias = conv_b[c];
        const __half* src = g_zxh + (size_t)b * SEQL * D_IN_PROJ + DINNER + c;
        __half* dst; int stride;
        if (c < DINNER) {
            dst = g_xs + (size_t)b * SEQL * DINNER + c;           stride = DINNER;
        } else if (c < DINNER + DSTATE) {
            dst = g_B + (size_t)b * SEQL * DSTATE + (c - DINNER); stride = DSTATE;
        } else {
            dst = g_C + (size_t)b * SEQL * DSTATE + (c - DINNER - DSTATE); stride = DSTATE;
        }
        dst += (size_t)t0 * stride;
        float x0 = (t0 >= 3) ? __half2float(src[(size_t)(t0 - 3) * D_IN_PROJ]) : 0.f;
        float x1 = (t0 >= 2) ? __half2float(src[(size_t)(t0 - 2) * D_IN_PROJ]) : 0.f;
        float x2 = (t0 >= 1) ? __half2float(src[(size_t)(t0 - 1) * D_IN_PROJ]) : 0.f;
        for (int t = 0; t < 256; t++) {
            float x3 = __half2float(src[(size_t)(t0 + t) * D_IN_PROJ]);
            float a = bias + w0 * x0 + w1 * x1 + w2 * x2 + w3 * x3;
            dst[(size_t)t * stride] = __float2half_rn(siluf(a));
            x0 = x1; x1 = x2; x2 = x3;
        }
    }
}

// ---------------- merged SSM operand transposes ----------------
__global__ void cvt_ssm_kernel()
{
    __shared__ float xs[64][65];
    __shared__ float dts[64], dec[64];
    __shared__ __half btile[32][34];
    int tid = threadIdx.x;
    if (blockIdx.x < 512) {
        int i = blockIdx.x;
        int t0 = (i & 63) * 32; i >>= 6;
        int n0 = (i & 3) * 32;
        int b = i >> 2;
#pragma unroll
        for (int it = 0; it < 4; it++) {
            int v = tid + it * 256;
            int t = v >> 5, n = v & 31;
            btile[t][n] = g_B[(size_t)(b * SEQL + t0 + t) * DSTATE + n0 + n];
        }
        __syncthreads();
#pragma unroll
        for (int it = 0; it < 2; it++) {
            int v = tid + it * 256;
            int n = v >> 4, tc = (v & 15) << 1;
            size_t o = (size_t)(b * DSTATE + n0 + n) * SEQL + t0 + tc;
            *(__half2*)(g_BT + o) = __halves2half2(btile[tc][n], btile[tc + 1][n]);
        }
    } else {
        int j = blockIdx.x - 512;
        int tt = j & 31; j >>= 5;
        int h = j & 63;
        int b = j >> 6;
        int t0 = tt * 64;
        int c = t0 >> 8;
        const float* acs = g_Acs + ((b * NHEADS + h) * NCHUNK + c) * CHUNKL;
        if (tid < 64) {
            int tl = (t0 & 255) + tid;
            dts[tid] = g_dt[(size_t)(b * SEQL + t0 + tid) * NHEADS + h];
            dec[tid] = __expf(acs[CHUNKL - 1] - acs[tl]);
        }
#pragma unroll
        for (int it = 0; it < 16; it++) {
            int v = tid + it * 256;
            int t = v >> 6, p = v & 63;
            xs[t][p] = __half2float(g_xs[(size_t)(b * SEQL + t0 + t) * DINNER + h * HEADDIM + p]);
        }
        __syncthreads();
#pragma unroll
        for (int it = 0; it < 8; it++) {
            int v = tid + it * 256;
            int p = v >> 5, tc = (v & 31) << 1;
            size_t o = ((size_t)((b * NHEADS + h) * HEADDIM) + p) * SEQL + t0 + tc;
            float x0 = xs[tc][p] * dts[tc];
            float x1 = xs[tc + 1][p] * dts[tc + 1];
            *(__half2*)(g_XdT + o)   = __floats2half2_rn(x0, x1);
            *(__half2*)(g_XdecT + o) = __floats2half2_rn(x0 * dec[tc], x1 * dec[tc + 1]);
        }
    }
}

// ---------------- states (single fp16 HMMA) -> fp16 output ----------------
#define S_A_O 0
#define S_B_O 2048
#define S_STG 6144
#define S_SMEM_BYTES (2 * S_STG * 4)

__global__ __launch_bounds__(256, 2) void states_hmma()
{
    extern __shared__ uint32_t sw[];
    const uint32_t sb = smem_u32(sw);
    int bid = blockIdx.x;
    int h = bid & 63, cc = (bid >> 6) & 7, b = bid >> 9;
    int tid = threadIdx.x, wid = tid >> 5, lane = tid & 31;
    int warp_m = wid >> 2, warp_n = wid & 3;
    const __half* A = g_XdecT + (size_t)((b * NHEADS + h) * HEADDIM) * SEQL + cc * CHUNKL;
    const __half* B = g_BT + (size_t)(b * DSTATE) * SEQL + cc * CHUNKL;

    float acc[2][4][4];
#pragma unroll
    for (int i = 0; i < 2; i++)
#pragma unroll
        for (int j = 0; j < 4; j++)
#pragma unroll
            for (int q = 0; q < 4; q++) acc[i][j][q] = 0.f;

    auto load_stage = [&](int kc, int buf) {
        uint32_t base = (uint32_t)buf * S_STG;
        int koff = kc * 64;
#pragma unroll
        for (int it = 0; it < 2; it++) {
            int v = tid + (it << 8);
            int r = v >> 3, ch = v & 7;
            int sch = ch ^ (r & 7);
            cp16(sb + (base + S_A_O + r * 32 + sch * 4) * 4, A + (size_t)r * SEQL + koff + ch * 8);
        }
#pragma unroll
        for (int it = 0; it < 4; it++) {
            int v = tid + (it << 8);
            int r = v >> 3, ch = v & 7;
            int sch = ch ^ (r & 7);
            cp16(sb + (base + S_B_O + r * 32 + sch * 4) * 4, B + (size_t)r * SEQL + koff + ch * 8);
        }
        asm volatile("cp.async.commit_group;" ::: "memory");
    };

    load_stage(0, 0);
    load_stage(1, 1);

    const int arow = warp_m * 32 + ((lane >> 3) & 1) * 8 + (lane & 7);
    const int cA0 = lane >> 4;
    const int brl = ((lane >> 4) & 1) * 8 + (lane & 7);
    const int cB0 = (lane >> 3) & 1;

    for (int kc = 0; kc < 4; kc++) {
        if (kc < 3) asm volatile("cp.async.wait_group 1;" ::: "memory");
        else        asm volatile("cp.async.wait_group 0;" ::: "memory");
        __syncthreads();
        uint32_t base = (uint32_t)(kc & 1) * S_STG;
#pragma unroll
        for (int kk = 0; kk < 4; kk++) {
            uint32_t a[2][4];
#pragma unroll
            for (int mi = 0; mi < 2; mi++) {
                int r = arow + mi * 16;
                uint32_t w = base + S_A_O + r * 32 + ((((kk << 1) + cA0) ^ (r & 7)) << 2);
                ldsm4(a[mi], sb + w * 4);
            }
#pragma unroll
            for (int np = 0; np < 2; np++) {
                int rb = warp_n * 32 + np * 16 + brl;
                uint32_t w = base + S_B_O + rb * 32 + ((((kk << 1) + cB0) ^ (rb & 7)) << 2);
                uint32_t bf[4];
                ldsm4(bf, sb + w * 4);
#pragma unroll
                for (int mi = 0; mi < 2; mi++) {
                    mma_fp16(acc[mi][2 * np], a[mi], bf);
                    mma_fp16(acc[mi][2 * np + 1], a[mi], bf + 2);
                }
            }
        }
        __syncthreads();
        if (kc + 2 < 4) load_stage(kc + 2, kc & 1);
    }

    __half* out = g_statesh + (size_t)((b * NCHUNK + cc) * NHEADS + h) * HEADDIM * DSTATE;
#pragma unroll
    for (int mi = 0; mi < 2; mi++) {
        int r0 = warp_m * 32 + mi * 16 + (lane >> 2);
#pragma unroll
        for (int ni = 0; ni < 4; ni++) {
            int col = warp_n * 32 + ni * 8 + 2 * (lane & 3);
            *(__half2*)(out + (size_t)r0 * DSTATE + col) =
                __floats2half2_rn(acc[mi][ni][0], acc[mi][ni][1]);
            *(__half2*)(out + (size_t)(r0 + 8) * DSTATE + col) =
                __floats2half2_rn(acc[mi][ni][2], acc[mi][ni][3]);
        }
    }
}

// ---------------- inter-chunk recurrence ----------------
__global__ __launch_bounds__(1024) void prev_kernel()
{
    int b = blockIdx.x >> 6;
    int h = blockIdx.x & 63;
    int tid = threadIdx.x;
    float P[8];
#pragma unroll
    for (int i = 0; i < 8; i++) P[i] = 0.f;
    for (int c = 0; c < NCHUNK; c++) {
        float decay = __expf(g_Acs[((b * NHEADS + h) * NCHUNK + c) * CHUNKL + CHUNKL - 1]);
        size_t base = (size_t)((b * NCHUNK + c) * NHEADS + h) * HEADDIM * DSTATE;
#pragma unroll
        for (int i = 0; i < 8; i++) {
            int e = i * 1024 + tid;
            float v = P[i];
            g_prev[base + e] = __float2half_rn(v);
            P[i] = v * decay + __half2float(g_statesh[base + e]);
        }
    }
}

// ---------------- Y via single fp16 HMMA -> fp16 out + fused sumsq ----------------
#define Y_ACS_O 0
#define Y_C_O 256
#define Y_PV_O (Y_C_O + 4352)
#define Y_B0_O (Y_PV_O + 4352)
#define Y_B1_O (Y_B0_O + 4352)
#define Y_X0_O (Y_B1_O + 4352)
#define Y_X1_O (Y_X0_O + 2304)
#define Y_S_O  (Y_X1_O + 2304)
#define Y_SMEM_BYTES ((Y_S_O + 2304) * 4)

__global__ __launch_bounds__(256, 2) void y_hmma(const float* __restrict__ Dp)
{
    extern __shared__ uint32_t sw[];
    const uint32_t sb = smem_u32(sw);
    float* acs_s = (float*)(sw + Y_ACS_O);
    int bid = blockIdx.x;
    int lt = bid & 3, h = (bid >> 2) & 63, c = (bid >> 8) & 7, b = bid >> 11;
    int tid = threadIdx.x, wid = tid >> 5, lane = tid & 31;
    int warp_m = wid >> 2, warp_n = wid & 3;
    int l0 = lt * 64;
    const int bt0 = b * SEQL + c * CHUNKL;

    acs_s[tid] = g_Acs[((b * NHEADS + h) * NCHUNK + c) * CHUNKL + tid];

    const __half* gB = g_B + (size_t)bt0 * DSTATE;
    const __half* gX = g_XdT + (size_t)((b * NHEADS + h) * HEADDIM) * SEQL + c * CHUNKL;

    auto load_bx = [&](int st, int pbuf) {
        const __half* Bp = gB + (size_t)(st * 64) * DSTATE;
        const __half* Xp = gX + st * 64;
        uint32_t bo = pbuf ? (uint32_t)Y_B1_O : (uint32_t)Y_B0_O;
        uint32_t xo = pbuf ? (uint32_t)Y_X1_O : (uint32_t)Y_X0_O;
#pragma unroll
        for (int it = 0; it < 4; it++) {
            int v = tid + (it << 8);
            int r = v >> 4, ch = v & 15;
            cp16(sb + (bo + r * 68 + ch * 4) * 4, Bp + (size_t)r * DSTATE + ch * 8);
        }
#pragma unroll
        for (int it = 0; it < 2; it++) {
            int v = tid + (it << 8);
            int r = v >> 3, ch = v & 7;
            cp16(sb + (xo + r * 36 + ch * 4) * 4, Xp + (size_t)r * SEQL + ch * 8);
        }
        asm volatile("cp.async.commit_group;" ::: "memory");
    };

    {
        const __half* sC = g_C + (size_t)(bt0 + l0) * DSTATE;
        size_t pb = (size_t)((b * NCHUNK + c) * NHEADS + h) * HEADDIM * DSTATE;
        const __half* sP = g_prev + pb;
#pragma unroll
        for (int it = 0; it < 4; it++) {
            int v = tid + (it << 8);
            int r = v >> 4, ch = v & 15;
            cp16(sb + (Y_C_O + r * 68 + ch * 4) * 4, sC + (size_t)r * DSTATE + ch * 8);
            cp16(sb + (Y_PV_O + r * 68 + ch * 4) * 4, sP + (size_t)r * DSTATE + ch * 8);
        }
        asm volatile("cp.async.commit_group;" ::: "memory");
    }
    load_bx(0, 0);

    asm volatile("cp.async.wait_group 1;" ::: "memory");
    __syncthreads();

    float Yacc[2][2][4];
#pragma unroll
    for (int i = 0; i < 2; i++)
#pragma unroll
        for (int j = 0; j < 2; j++)
#pragma unroll
            for (int q = 0; q < 4; q++) Yacc[i][j][q] = 0.f;

    const int arow = warp_m * 32 + ((lane >> 3) & 1) * 8 + (lane & 7);
    const int akw  = (lane >> 4) << 2;
    const int brow = warp_n * 16 + ((lane >> 4) & 1) * 8 + (lane & 7);
    const int bkw  = ((lane >> 3) & 1) << 2;

#pragma unroll
    for (int kk = 0; kk < 8; kk++) {
        uint32_t a[2][4], bf[4];
#pragma unroll
        for (int mi = 0; mi < 2; mi++)
            ldsm4(a[mi], sb + (uint32_t)(Y_C_O + (arow + mi * 16) * 68 + kk * 8 + akw) * 4);
        ldsm4(bf, sb + (uint32_t)(Y_PV_O + brow * 68 + kk * 8 + bkw) * 4);
#pragma unroll
        for (int mi = 0; mi < 2; mi++) {
            mma_fp16(Yacc[mi][0], a[mi], bf);
            mma_fp16(Yacc[mi][1], a[mi], bf + 2);
        }
    }
#pragma unroll
    for (int mi = 0; mi < 2; mi++) {
        int r0 = l0 + warp_m * 32 + mi * 16 + (lane >> 2);
        float e0 = __expf(acs_s[r0]);
        float e1 = __expf(acs_s[r0 + 8]);
#pragma unroll
        for (int ni = 0; ni < 2; ni++) {
            Yacc[mi][ni][0] *= e0; Yacc[mi][ni][1] *= e0;
            Yacc[mi][ni][2] *= e1; Yacc[mi][ni][3] *= e1;
        }
    }

    for (int st = 0; st <= lt; st++) {
        if (st + 1 <= lt) {
            load_bx(st + 1, (st + 1) & 1);
            asm volatile("cp.async.wait_group 1;" ::: "memory");
        } else {
            asm volatile("cp.async.wait_group 0;" ::: "memory");
        }
        __syncthreads();

        const uint32_t bo = (st & 1) ? (uint32_t)Y_B1_O : (uint32_t)Y_B0_O;
        const uint32_t xo = (st & 1) ? (uint32_t)Y_X1_O : (uint32_t)Y_X0_O;
        int s0 = st * 64;

        float sacc[2][2][4];
#pragma unroll
        for (int i = 0; i < 2; i++)
#pragma unroll
            for (int j = 0; j < 2; j++)
#pragma unroll
                for (int q = 0; q < 4; q++) sacc[i][j][q] = 0.f;
#pragma unroll
        for (int kk = 0; kk < 8; kk++) {
            uint32_t a[2][4], bf[4];
#pragma unroll
            for (int mi = 0; mi < 2; mi++)
                ldsm4(a[mi], sb + (uint32_t)(Y_C_O + (arow + mi * 16) * 68 + kk * 8 + akw) * 4);
            ldsm4(bf, sb + (bo + brow * 68 + kk * 8 + bkw) * 4);
#pragma unroll
            for (int mi = 0; mi < 2; mi++) {
                mma_fp16(sacc[mi][0], a[mi], bf);
                mma_fp16(sacc[mi][1], a[mi], bf + 2);
            }
        }
#pragma unroll
        for (int mi = 0; mi < 2; mi++) {
            int rr0 = warp_m * 32 + mi * 16 + (lane >> 2);
            int lg0 = l0 + rr0, lg1 = lg0 + 8;
            float a0 = acs_s[lg0], a1 = acs_s[lg1];
#pragma unroll
            for (int ni = 0; ni < 2; ni++) {
                int ccc = warp_n * 16 + ni * 8 + 2 * (lane & 3);
                int sg = s0 + ccc;
                float as0 = acs_s[sg], as1 = acs_s[sg + 1];
                float v00 = (sg     <= lg0) ? sacc[mi][ni][0] * __expf(a0 - as0) : 0.f;
                float v01 = (sg + 1 <= lg0) ? sacc[mi][ni][1] * __expf(a0 - as1) : 0.f;
                float v10 = (sg     <= lg1) ? sacc[mi][ni][2] * __expf(a1 - as0) : 0.f;
                float v11 = (sg + 1 <= lg1) ? sacc[mi][ni][3] * __expf(a1 - as1) : 0.f;
                sw[Y_S_O + rr0 * 36 + (ccc >> 1)] =
                    packh2(__float2half_rn(v00), __float2half_rn(v01));
                sw[Y_S_O + (rr0 + 8) * 36 + (ccc >> 1)] =
                    packh2(__float2half_rn(v10), __float2half_rn(v11));
            }
        }
        __syncthreads();
#pragma unroll
        for (int kk = 0; kk < 4; kk++) {
            uint32_t a[2][4], bf[4];
#pragma unroll
            for (int mi = 0; mi < 2; mi++)
                ldsm4(a[mi], sb + (uint32_t)(Y_S_O + (arow + mi * 16) * 36 + kk * 8 + akw) * 4);
            ldsm4(bf, sb + (xo + brow * 36 + kk * 8 + bkw) * 4);
#pragma unroll
            for (int mi = 0; mi < 2; mi++) {
                mma_fp16(Yacc[mi][0], a[mi], bf);
                mma_fp16(Yacc[mi][1], a[mi], bf + 2);
            }
        }
    }

    // epilogue: + D*x_ssm, gate silu(z fp16), fp16 store + row sumsq atomics
    float Dh = Dp[h];
#pragma unroll
    for (int mi = 0; mi < 2; mi++) {
#pragma unroll
        for (int q = 0; q < 2; q++) {
            int rr = warp_m * 32 + mi * 16 + (lane >> 2) + q * 8;
            int t = bt0 + l0 + rr;
            float local = 0.f;
#pragma unroll
            for (int ni = 0; ni < 2; ni++) {
                int pp = warp_n * 16 + ni * 8 + 2 * (lane & 3);
                float2 xs = __half22float2(*(const __half2*)(g_xs + (size_t)t * DINNER + h * HEADDIM + pp));
                float2 zz = __half22float2(*(const __half2*)(g_zxh + (size_t)t * D_IN_PROJ + h * HEADDIM + pp));
                float y0 = (Yacc[mi][ni][q * 2 + 0] + xs.x * Dh) * siluf(zz.x);
                float y1 = (Yacc[mi][ni][q * 2 + 1] + xs.y * Dh) * siluf(zz.y);
                *(__half2*)(g_ygh + (size_t)t * DINNER + h * HEADDIM + pp) = __floats2half2_rn(y0, y1);
                local += y0 * y0 + y1 * y1;
            }
            local += __shfl_xor_sync(0xFFFFFFFFu, local, 1);
            local += __shfl_xor_sync(0xFFFFFFFFu, local, 2);
            if ((lane & 3) == 0) atomicAdd(&g_ss[t], local);
        }
    }
}

// ---------------- launch ----------------
extern "C" void kernel_launch(void* const* d_in, const int* in_sizes, int n_in,
                              void* d_out, int out_size)
{
    const float* x          = (const float*)d_in[0];
    const float* in_proj_w  = (const float*)d_in[1];
    const float* conv_w     = (const float*)d_in[2];
    const float* conv_b     = (const float*)d_in[3];
    const float* dt_bias    = (const float*)d_in[4];
    const float* A_log      = (const float*)d_in[5];
    const float* Dp         = (const float*)d_in[6];
    const float* norm_w     = (const float*)d_in[7];
    const float* out_proj_w = (const float*)d_in[8];
    float* out = (float*)d_out;

    float *ss_p = nullptr, *dtraw_p = nullptr;
    __half *zxh_p, *xh_p, *wih_p, *ygh_p, *owh_p;
    cudaGetSymbolAddress((void**)&ss_p, g_ss);
    cudaGetSymbolAddress((void**)&dtraw_p, g_dtraw);
    cudaGetSymbolAddress((void**)&zxh_p, g_zxh);
    cudaGetSymbolAddress((void**)&xh_p, g_xh);
    cudaGetSymbolAddress((void**)&wih_p, g_wih);
    cudaGetSymbolAddress((void**)&ygh_p, g_ygh);
    cudaGetSymbolAddress((void**)&owh_p, g_owh);

    static bool attr_set = false;
    if (!attr_set) {
        cudaFuncSetAttribute(gemm_hmma_out<__half>, cudaFuncAttributeMaxDynamicSharedMemorySize, GEMM1_SMEM);
        cudaFuncSetAttribute(gemm_hmma_out<float>, cudaFuncAttributeMaxDynamicSharedMemorySize, GEMM1_SMEM);
        cudaFuncSetAttribute(states_hmma, cudaFuncAttributeMaxDynamicSharedMemorySize, S_SMEM_BYTES);
        cudaFuncSetAttribute(y_hmma, cudaFuncAttributeMaxDynamicSharedMemorySize, Y_SMEM_BYTES);
        attr_set = true;
    }

    const int M = B_SZ * SEQL; // 4096

    // 0) merged converts (out_proj_w pre-multiplied by norm_w)
    cvt_all<<<CVT_B1 + CVT_B2 + CVT_B3, 256>>>(x, in_proj_w, out_proj_w, norm_w,
                                               xh_p, wih_p, owh_p);

    // 1) in_proj GEMM -> fp16 zx + fp32 dt-raw side copy
    gemm_hmma_out<__half><<<dim3(DIP_PAD / 128, M / 128), 256, GEMM1_SMEM>>>(
        xh_p, wih_p, zxh_p, M, D_IN_PROJ, DMODEL, dtraw_p, nullptr);

    // zero sumsq for y_hmma accumulation
    cudaMemsetAsync(ss_p, 0, B_SZ * SEQL * sizeof(float));

    // 2+3) conv+silu and dt softplus+cumsum, merged
    conv_dt_kernel<<<1024 + 17 * B_SZ * (SEQL / 256), 256>>>(conv_w, conv_b, dt_bias, A_log);

    // 4) SSM operand transposes, merged
    cvt_ssm_kernel<<<512 + (SEQL / 64) * NHEADS * B_SZ, 256>>>();

    // 5) states
    states_hmma<<<B_SZ * NCHUNK * NHEADS, 256, S_SMEM_BYTES>>>();

    // 6) recurrence
    prev_kernel<<<B_SZ * NHEADS, 1024>>>();

    // 7) Y + gate + sumsq
    y_hmma<<<B_SZ * NCHUNK * NHEADS * 4, 256, Y_SMEM_BYTES>>>(Dp);

    // 8) out_proj GEMM (A = ygh, W pre-fused with norm_w, row scale in epilogue)
    gemm_hmma_out<float><<<dim3(DMODEL / 128, M / 128), 256, GEMM1_SMEM>>>(
        ygh_p, owh_p, out, M, DMODEL, DINNER, nullptr, ss_p);

    (void)in_sizes; (void)n_in; (void)out_size;
}